// round 7
// baseline (speedup 1.0000x reference)
#include <cuda_runtime.h>
#include <cstdint>

#define T_STEPS 64
#define BB      8
#define IN_DIM  256
#define HH      512
#define H3      1536
#define NBLK    128
#define NTHR    512
#define AGG     127

// ---------------- output offsets (floats) ----------------
#define OUT_V      0ull
#define OUT_H      4096ull
#define OUT_DUF    8192ull
#define OUT_TEF    2105344ull
#define OUT_TEMAT  2109440ull
#define OUT_OUTS   4206592ull
#define OUT_DUS    4468736ull
#define OUT_MODS   138686464ull
#define OUT_SS     138735616ull
#define OUT_MS     138736128ull
#define OUT_RS     138736640ull

// ---------------- smem layout (float index) ----------------
#define S_TEM  0        /* [32][512] trace_E matrix */
#define S_WH   16384    /* [8][1536] staging */
#define S_H    28672    /* [8][512]  */
#define S_HFW  32768    /* [8][512]  */
#define S_TE   36864    /* [8][512]  */
#define S_ZW   40960    /* [8][512] zo weight rows */
#define S_FWP  45056    /* [32][4] */
#define S_MOD  45184    /* [8][96] = 768 */
#define S_SCAL 45952    /* r[8] s[8] m[8] */
#define S_RED  45984    /* [32] */
#define S_MU   46016    /* [8] */
#define S_RS   46024    /* [8] */
#define SMEM_FLOATS 46032
// prologue overlay: sX [0,1024) + wtile [1024,14848) inside S_TEM

// ---------------- device globals ----------------
__device__ float    g_wx[T_STEPS * BB * H3];
__device__ float    g_whbuf[2][BB * H3];
__device__ unsigned g_lineA[NBLK][32];    // [0]=flag (128B padded)
__device__ unsigned g_epochA;

// ---------------- helpers ----------------
__device__ __forceinline__ unsigned ld_acq(const unsigned* p) {
    unsigned v;
    asm volatile("ld.global.acquire.gpu.b32 %0, [%1];" : "=r"(v) : "l"(p) : "memory");
    return v;
}
__device__ __forceinline__ void st_rel(unsigned* p, unsigned v) {
    asm volatile("st.global.release.gpu.b32 [%0], %1;" :: "l"(p), "r"(v) : "memory");
}
__device__ __forceinline__ float sigm(float x) { return 1.f / (1.f + __expf(-x)); }
__device__ __forceinline__ float dot4(float4 a, float4 b) {
    return fmaf(a.x, b.x, fmaf(a.y, b.y, fmaf(a.z, b.z, a.w * b.w)));
}
__device__ __forceinline__ float wred(float v) {
#pragma unroll
    for (int o = 16; o; o >>= 1) v += __shfl_down_sync(0xffffffffu, v, o);
    return v;
}
__device__ __forceinline__ float wxor(float v) {
#pragma unroll
    for (int o = 16; o; o >>= 1) v += __shfl_xor_sync(0xffffffffu, v, o);
    return v;
}
__device__ __forceinline__ void block_sum2(float& a, float& b, float* sRed) {
#pragma unroll
    for (int o = 16; o; o >>= 1) {
        a += __shfl_down_sync(0xffffffffu, a, o);
        b += __shfl_down_sync(0xffffffffu, b, o);
    }
    __syncthreads();
    const int w = threadIdx.x >> 5;
    if ((threadIdx.x & 31) == 0) { sRed[w] = a; sRed[16 + w] = b; }
    __syncthreads();
    float ra = 0.f, rb = 0.f;
#pragma unroll
    for (int i = 0; i < 16; i++) { ra += sRed[i]; rb += sRed[16 + i]; }
    a = ra; b = rb;
}

__global__ void zero_flags_kernel() {
    int t = threadIdx.x;
    if (t < NBLK) g_lineA[t][0] = 0u;
    if (t == 0)   g_epochA = 0u;
}

// ====================================================================
__global__ void __launch_bounds__(NTHR, 1)
sgru_main(const float* __restrict__ x,       const float* __restrict__ h_in,
          const float* __restrict__ v_in,    const float* __restrict__ dU_in,
          const float* __restrict__ te_in,   const float* __restrict__ tE_in,
          const float* __restrict__ x2h_w,   const float* __restrict__ x2h_b,
          const float* __restrict__ h2h_w,   const float* __restrict__ h2h_b,
          const float* __restrict__ lnx_g,   const float* __restrict__ lnx_b,
          const float* __restrict__ lnh_g,   const float* __restrict__ lnh_b,
          const float* __restrict__ h2mod_w, const float* __restrict__ h2mod_b,
          const float* __restrict__ m2r_w,   const float* __restrict__ m2r_b,
          const float* __restrict__ m2s_w,   const float* __restrict__ m2s_b,
          const float* __restrict__ m2m_w,   const float* __restrict__ m2m_b,
          const float* __restrict__ alpha_p, const float* __restrict__ tauU_p,
          float* __restrict__ out)
{
    extern __shared__ float sm[];
    const int tid = threadIdx.x;
    const int bk  = blockIdx.x;
    const int wid = tid >> 5, lid = tid & 31;
    const int i0  = bk * 4;
    const int g   = tid >> 7;        // il group 0..3
    const int q   = tid & 127;       // quad index
    const int i   = i0 + g;

    float*  sWh   = sm + S_WH;
    float*  sH    = sm + S_H;
    float*  sHfw  = sm + S_HFW;
    float*  sTe   = sm + S_TE;
    float*  sZW   = sm + S_ZW;
    float*  sFwP  = sm + S_FWP;
    float*  sMod  = sm + S_MOD;      // [b][96]
    float*  sScal = sm + S_SCAL;
    float*  sRed  = sm + S_RED;
    float*  sMu   = sm + S_MU;
    float*  sRs   = sm + S_RS;
    float4* sTE4  = (float4*)(sm + S_TEM);
    float4* sH4   = (float4*)sH;
    float4* sHfw4 = (float4*)sHfw;
    float4* sTe4  = (float4*)sTe;

    const float spa     = log1pf(expf(alpha_p[0]));
    const float inv_spe = 1.f / (spa + 1e-8f);
    const float tau     = 1.f / (1.f + expf(-tauU_p[0]));
    const float omtau   = 1.f - tau;

    // ================= PROLOGUE A: g_wx = LN(x @ x2h^T + b) =================
    {
        float* sX    = sm;           // [4][256]
        float* wtile = sm + 1024;    // [1536][9]
        const int rg0 = bk * 4;

        float acc[4][3];
#pragma unroll
        for (int r = 0; r < 4; r++)
#pragma unroll
            for (int p = 0; p < 3; p++) acc[r][p] = 0.f;

        for (int idx = tid; idx < 4 * IN_DIM; idx += NTHR)
            sX[idx] = x[(size_t)rg0 * IN_DIM + idx];

        for (int ct = 0; ct < 32; ++ct) {
            const int c0 = ct * 8;
            __syncthreads();
            for (int idx = tid; idx < H3 * 8; idx += NTHR) {
                int kl = idx >> 3, c = idx & 7;
                wtile[kl * 9 + c] = x2h_w[(size_t)kl * IN_DIM + c0 + c];
            }
            __syncthreads();
            float xv[4][8];
#pragma unroll
            for (int r = 0; r < 4; r++)
#pragma unroll
                for (int c = 0; c < 8; c++) xv[r][c] = sX[r * IN_DIM + c0 + c];
#pragma unroll
            for (int p = 0; p < 3; p++) {
                const int kk = tid + NTHR * p;
                float wv[8];
#pragma unroll
                for (int c = 0; c < 8; c++) wv[c] = wtile[kk * 9 + c];
#pragma unroll
                for (int r = 0; r < 4; r++)
#pragma unroll
                    for (int c = 0; c < 8; c++)
                        acc[r][p] = fmaf(wv[c], xv[r][c], acc[r][p]);
            }
        }
#pragma unroll
        for (int p = 0; p < 3; p++) {
            const float bq = x2h_b[tid + NTHR * p];
#pragma unroll
            for (int r = 0; r < 4; r++) acc[r][p] += bq;
        }
#pragma unroll
        for (int r = 0; r < 4; r++) {
            float s1 = 0.f, s2 = 0.f;
#pragma unroll
            for (int p = 0; p < 3; p++) { float v = acc[r][p]; s1 += v; s2 = fmaf(v, v, s2); }
            block_sum2(s1, s2, sRed);
            const float mu   = s1 * (1.f / H3);
            const float rstd = rsqrtf(s2 * (1.f / H3) - mu * mu + 1e-5f);
            float* wrow = g_wx + (size_t)(rg0 + r) * H3;
#pragma unroll
            for (int p = 0; p < 3; p++) {
                const int kk = tid + NTHR * p;
                wrow[kk] = (acc[r][p] - mu) * rstd * lnx_g[kk] + lnx_b[kk];
            }
        }
        __syncthreads();
    }

    // ================= PROLOGUE B: persistent state =================
    float4 rDU4[8], w4, up4, lo4;
    float vr[8];
    {
        w4 = ((const float4*)(h2h_w + (size_t)(2 * HH + i) * HH))[q];
        up4.x =  fmaxf(1.f - w4.x, 0.f) * inv_spe;  lo4.x = -fmaxf(1.f + w4.x, 0.f) * inv_spe;
        up4.y =  fmaxf(1.f - w4.y, 0.f) * inv_spe;  lo4.y = -fmaxf(1.f + w4.y, 0.f) * inv_spe;
        up4.z =  fmaxf(1.f - w4.z, 0.f) * inv_spe;  lo4.z = -fmaxf(1.f + w4.z, 0.f) * inv_spe;
        up4.w =  fmaxf(1.f - w4.w, 0.f) * inv_spe;  lo4.w = -fmaxf(1.f + w4.w, 0.f) * inv_spe;
#pragma unroll
        for (int b = 0; b < 8; b++) {
            const size_t g4 = (size_t)(b * HH + i) * 128 + q;
            rDU4[b] = ((const float4*)dU_in)[g4];
            sTE4[(g * 8 + b) * 128 + q] = ((const float4*)tE_in)[g4];
        }
        for (int idx = tid; idx < 8 * HH; idx += NTHR) {
            const int w = idx >> 9, j = idx & 511;
            sZW[idx] = h2h_w[(size_t)(bk * 8 + w) * HH + j];
        }
#pragma unroll
        for (int b = 0; b < 8; b++) {
            vr[b] = v_in[b * HH + tid];
            sTe[b * HH + tid] = te_in[b * HH + tid];
            sH [b * HH + tid] = h_in[b * HH + tid];
        }
        __syncthreads();
    }

    // ---- pre-loop: zo GEMM for step 0 ----
    if (wid < 8) {
        const int k = bk * 8 + wid;
        float accA[8];
#pragma unroll
        for (int b = 0; b < 8; b++) accA[b] = 0.f;
#pragma unroll
        for (int c = 0; c < 4; c++) {
            const float4 wv = ((const float4*)&sZW[wid * HH])[lid + 32 * c];
#pragma unroll
            for (int b = 0; b < 8; b++)
                accA[b] += dot4(wv, sH4[b * 128 + lid + 32 * c]);
        }
        const float bias = h2h_b[k];
#pragma unroll
        for (int b = 0; b < 8; b++) {
            float v = wxor(accA[b]);
            if (lid == b) __stcg(&g_whbuf[0][b * H3 + k], v + bias);
        }
    }

    // ================= MAIN LOOP =================
    for (int it = 0; it <= T_STEPS; ++it) {
        const bool last = (it == T_STEPS);
        float* whb = g_whbuf[it & 1];

        // ---- B: trace update (step it-1) + fused dv partials (step it) ----
        float tnew[8];
#pragma unroll
        for (int b = 0; b < 8; b++) {
            if (it > 0) {
                const float rb  = sScal[b];
                const float sb  = sScal[8 + b];
                const float mb  = sScal[16 + b];
                const float oms = 1.f - sb;
                const float tm  = tau * mb;
                const float hfi = sHfw[b * HH + i];
                const float tei = sTe [b * HH + i];
                const float4 teo4 = sTe4 [b * 128 + q];
                const float4 hf4  = sHfw4[b * 128 + q];
                float4 t4 = sTE4[(g * 8 + b) * 128 + q];
                t4.x = oms * t4.x + sb * (hfi * teo4.x - tei * hf4.x);
                t4.y = oms * t4.y + sb * (hfi * teo4.y - tei * hf4.y);
                t4.z = oms * t4.z + sb * (hfi * teo4.z - tei * hf4.z);
                t4.w = oms * t4.w + sb * (hfi * teo4.w - tei * hf4.w);
                sTE4[(g * 8 + b) * 128 + q] = t4;
                float4 d4 = rDU4[b];
                d4.x = fmaxf(fminf(omtau * d4.x + tm * t4.x, up4.x), lo4.x);
                d4.y = fmaxf(fminf(omtau * d4.y + tm * t4.y, up4.y), lo4.y);
                d4.z = fmaxf(fminf(omtau * d4.z + tm * t4.z, up4.z), lo4.z);
                d4.w = fmaxf(fminf(omtau * d4.w + tm * t4.w, up4.w), lo4.w);
                rDU4[b] = d4;
                tnew[b] = (1.f - rb) * sTe[b * HH + tid] + rb * sHfw[b * HH + tid];
            }
            if (!last) {
                const float4 h4 = sH4[b * 128 + q];
                const float4 d4 = rDU4[b];
                float p = (w4.x + spa * d4.x) * h4.x;
                p = fmaf(w4.y + spa * d4.y, h4.y, p);
                p = fmaf(w4.z + spa * d4.z, h4.z, p);
                p = fmaf(w4.w + spa * d4.w, h4.w, p);
                p = wred(p);
                if (lid == 0) sFwP[(g * 8 + b) * 4 + (wid & 3)] = p;
            }
        }
        __syncthreads();
        if (it > 0) {
#pragma unroll
            for (int b = 0; b < 8; b++) sTe[b * HH + tid] = tnew[b];
        }

        if (last) break;

        // ---- C: dv combine + publish flagA ----
        if (tid < 32) {
            const float v = sFwP[tid * 4] + sFwP[tid * 4 + 1] + sFwP[tid * 4 + 2] + sFwP[tid * 4 + 3];
            const int b = tid & 7, gg = tid >> 3;
            const int k = 2 * HH + i0 + gg;
            __stcg(&whb[b * H3 + k], v + h2h_b[k]);
        }
        __syncthreads();
        if (tid == 0) st_rel(&g_lineA[bk][0], (unsigned)(it + 1));

        // ---- D: aggregator hop + shadow work + epoch wait ----
        if (bk == AGG) {
            for (;;) {
                int ok = 1;
                if (tid < NBLK) ok = (ld_acq(&g_lineA[tid][0]) >= (unsigned)(it + 1));
                if (__syncthreads_count(ok) == NTHR) break;
            }
            if (tid == 0) st_rel(&g_epochA, (unsigned)(it + 1));
        }
        // shadow: dUs(it-1) store
        if (it > 0) {
            float4* dus4 = (float4*)(out + OUT_DUS + (size_t)(it - 1) * (BB * HH * HH));
#pragma unroll
            for (int b = 0; b < 8; b++)
                __stcs(&dus4[(size_t)(b * HH + i) * 128 + q], rDU4[b]);
        }
        // shadow: g_wx prefetch into registers
        float wx0[8], wx1[8], wx2[8];
        {
            const float* wxg = g_wx + (size_t)it * (BB * H3);
#pragma unroll
            for (int b = 0; b < 8; b++) {
                wx0[b] = __ldcg(&wxg[b * H3 + tid]);
                wx1[b] = __ldcg(&wxg[b * H3 + HH + tid]);
                wx2[b] = __ldcg(&wxg[b * H3 + 2 * HH + tid]);
            }
        }
        // wait epoch
        if (tid == 0) { while (ld_acq(&g_epochA) < (unsigned)(it + 1)) {} }
        __syncthreads();

        // ---- E: Wh load fused with LN stats, then gates ----
        {
            const int b = tid >> 6, l6 = tid & 63;
            float s1 = 0.f, s2 = 0.f;
#pragma unroll
            for (int p = 0; p < 24; p++) {
                const float v = __ldcg(&whb[b * H3 + l6 + 64 * p]);
                sWh[b * H3 + l6 + 64 * p] = v;
                s1 += v; s2 = fmaf(v, v, s2);
            }
#pragma unroll
            for (int o = 16; o; o >>= 1) {
                s1 += __shfl_down_sync(0xffffffffu, s1, o);
                s2 += __shfl_down_sync(0xffffffffu, s2, o);
            }
            if (lid == 0) { sRed[wid * 2] = s1; sRed[wid * 2 + 1] = s2; }
            __syncthreads();
            if (tid < 8) {
                const float t1 = sRed[tid * 4] + sRed[tid * 4 + 2];
                const float t2 = sRed[tid * 4 + 1] + sRed[tid * 4 + 3];
                const float mu = t1 * (1.f / H3);
                sMu[tid] = mu;
                sRs[tid] = rsqrtf(t2 * (1.f / H3) - mu * mu + 1e-5f);
            }
            __syncthreads();
        }
        {
            const float lg0 = lnh_g[tid],          lb0 = lnh_b[tid];
            const float lg1 = lnh_g[HH + tid],     lb1 = lnh_b[HH + tid];
            const float lg2 = lnh_g[2 * HH + tid], lb2 = lnh_b[2 * HH + tid];
#pragma unroll
            for (int b = 0; b < 8; b++) {
                const float mu = sMu[b], rs = sRs[b];
                const float pz = (sWh[b * H3 + tid]          - mu) * rs * lg0 + lb0 + wx0[b];
                const float po = (sWh[b * H3 + HH + tid]     - mu) * rs * lg1 + lb1 + wx1[b];
                const float pd = (sWh[b * H3 + 2 * HH + tid] - mu) * rs * lg2 + lb2 + wx2[b];
                const float z = sigm(pz);
                const float o = sigm(po);
                vr[b] = (1.f - z) * vr[b] + z * pd;
                const float nh = fmaxf(vr[b], 0.f);
                const float hf = o * nh;
                sH  [b * HH + tid] = nh;
                sHfw[b * HH + tid] = hf;
                if (bk == 32 + b)
                    out[OUT_OUTS + (size_t)it * (BB * HH) + b * HH + tid] = nh;
            }
        }
        __syncthreads();

        // ---- F: split — warps 0..7: zo GEMM (step it+1); warps 8..15: mod GEMM ----
        if (wid < 8) {
            if (it + 1 < T_STEPS) {
                float* whn = g_whbuf[(it + 1) & 1];
                const int k = bk * 8 + wid;
                float accA[8];
#pragma unroll
                for (int b = 0; b < 8; b++) accA[b] = 0.f;
#pragma unroll
                for (int c = 0; c < 4; c++) {
                    const float4 wv = ((const float4*)&sZW[wid * HH])[lid + 32 * c];
#pragma unroll
                    for (int b = 0; b < 8; b++)
                        accA[b] += dot4(wv, sH4[b * 128 + lid + 32 * c]);
                }
                const float bias = h2h_b[k];
#pragma unroll
                for (int b = 0; b < 8; b++) {
                    float v = wxor(accA[b]);
                    if (lid == b) __stcg(&whn[b * H3 + k], v + bias);
                }
            }
        } else {
            // mod rows: warp (wid-8) handles 12 rows x 8 batches
            const int w8 = wid - 8;
#pragma unroll
            for (int rr = 0; rr < 12; rr++) {
                const int row = w8 * 12 + rr;
                const float4* mw = (const float4*)(h2mod_w + (size_t)row * HH);
                float4 mw4[4];
#pragma unroll
                for (int c = 0; c < 4; c++) mw4[c] = __ldcg(&mw[lid + 32 * c]);
                float acc[8];
#pragma unroll
                for (int b = 0; b < 8; b++) {
                    float a = 0.f;
#pragma unroll
                    for (int c = 0; c < 4; c++)
                        a += dot4(mw4[c], sH4[b * 128 + lid + 32 * c]);
                    acc[b] = a;
                }
                const float mb = h2mod_b[row];
#pragma unroll
                for (int b = 0; b < 8; b++) {
                    float a = wxor(acc[b]);
                    if (lid == b) sMod[b * 96 + row] = fmaxf(a + mb, 0.f);
                }
            }
        }
        __syncthreads();

        // designated MODS writers
        if (bk >= 40 && bk < 48) {
            const int b = bk - 40;
            if (tid < 96)
                out[OUT_MODS + (size_t)it * (BB * 96) + b * 96 + tid] = sMod[b * 96 + tid];
        }
        // scalars: warps 0..2 (sc = wid), 8 batches each
        if (wid < 3) {
            const float* ww = (wid == 0) ? m2r_w : (wid == 1) ? m2s_w : m2m_w;
            const float wv = ww[lid];
            const float bb0 = (wid == 0) ? m2r_b[0] : (wid == 1) ? m2s_b[0] : m2m_b[0];
#pragma unroll
            for (int b = 0; b < 8; b++) {
                float a = wxor(sMod[b * 96 + wid * 32 + lid] * wv);
                if (lid == 0) {
                    float val;
                    if (wid == 0)      val = sigm(a + bb0);
                    else if (wid == 1) val = sigm(a + bb0);
                    else { const float mm = a + bb0; val = mm - tanhf(mm); }
                    sScal[wid * 8 + b] = val;
                    if (bk == 48 + b) {
                        const size_t off = (wid == 0) ? OUT_RS : (wid == 1) ? OUT_SS : OUT_MS;
                        out[off + (size_t)it * BB + b] = val;
                    }
                }
            }
        }
        __syncthreads();
    }

    // ================= EPILOGUE =================
    {
        float4* dus4 = (float4*)(out + OUT_DUS + (size_t)(T_STEPS - 1) * (BB * HH * HH));
        float4* duf4 = (float4*)(out + OUT_DUF);
        float4* tem4 = (float4*)(out + OUT_TEMAT);
#pragma unroll
        for (int b = 0; b < 8; b++) {
            const size_t g4 = (size_t)(b * HH + i) * 128 + q;
            dus4[g4] = rDU4[b];
            duf4[g4] = rDU4[b];
            tem4[g4] = sTE4[(g * 8 + b) * 128 + q];
        }
    }
    if (bk < BB) {
        out[OUT_V   + bk * HH + tid] = vr[bk];
        out[OUT_H   + bk * HH + tid] = sH[bk * HH + tid];
        out[OUT_TEF + bk * HH + tid] = sTe[bk * HH + tid];
    }
}

// ====================================================================
extern "C" void kernel_launch(void* const* d_in, const int* in_sizes, int n_in,
                              void* d_out, int out_size) {
    const float* x       = (const float*)d_in[0];
    const float* h       = (const float*)d_in[1];
    const float* v       = (const float*)d_in[2];
    const float* dU      = (const float*)d_in[3];
    const float* te      = (const float*)d_in[4];
    const float* tE      = (const float*)d_in[5];
    const float* x2h_w   = (const float*)d_in[6];
    const float* x2h_b   = (const float*)d_in[7];
    const float* h2h_w   = (const float*)d_in[8];
    const float* h2h_b   = (const float*)d_in[9];
    const float* lnx_g   = (const float*)d_in[10];
    const float* lnx_b   = (const float*)d_in[11];
    const float* lnh_g   = (const float*)d_in[12];
    const float* lnh_b   = (const float*)d_in[13];
    const float* h2mod_w = (const float*)d_in[14];
    const float* h2mod_b = (const float*)d_in[15];
    const float* m2r_w   = (const float*)d_in[16];
    const float* m2r_b   = (const float*)d_in[17];
    const float* m2s_w   = (const float*)d_in[18];
    const float* m2s_b   = (const float*)d_in[19];
    const float* m2m_w   = (const float*)d_in[20];
    const float* m2m_b   = (const float*)d_in[21];
    const float* alpha   = (const float*)d_in[22];
    const float* tauU    = (const float*)d_in[23];
    float* out = (float*)d_out;

    const size_t smem = (size_t)SMEM_FLOATS * sizeof(float);
    cudaFuncSetAttribute(sgru_main, cudaFuncAttributeMaxDynamicSharedMemorySize, (int)smem);

    zero_flags_kernel<<<1, 128>>>();
    sgru_main<<<NBLK, NTHR, smem>>>(x, h, v, dU, te, tE,
                                    x2h_w, x2h_b, h2h_w, h2h_b,
                                    lnx_g, lnx_b, lnh_g, lnh_b,
                                    h2mod_w, h2mod_b,
                                    m2r_w, m2r_b, m2s_w, m2s_b, m2m_w, m2m_b,
                                    alpha, tauU, out);
}

// round 8
// speedup vs baseline: 1.1173x; 1.1173x over previous
#include <cuda_runtime.h>
#include <cstdint>

#define T_STEPS 64
#define BB      8
#define IN_DIM  256
#define HH      512
#define H3      1536
#define NBLK    128
#define NTHR    512
#define AGG     0
#define NSCAL   24

// ---------------- output offsets (floats) ----------------
#define OUT_V      0ull
#define OUT_H      4096ull
#define OUT_DUF    8192ull
#define OUT_TEF    2105344ull
#define OUT_TEMAT  2109440ull
#define OUT_OUTS   4206592ull
#define OUT_DUS    4468736ull
#define OUT_MODS   138686464ull
#define OUT_SS     138735616ull
#define OUT_MS     138736128ull
#define OUT_RS     138736640ull

// ---------------- smem layout (float index) ----------------
#define S_TEM  0        /* [32][512] trace_E matrix */
#define S_WH   16384    /* [8][1536] staging */
#define S_H    28672    /* [8][512]  */
#define S_HFW  32768    /* [8][512]  */
#define S_TE   36864    /* [8][512]  */
#define S_ZW   40960    /* [10][512] zo weight rows */
#define S_FWP  46080    /* [32][4] */
#define S_MOD  46208    /* [32] pad 64 */
#define S_SCAL 46272    /* r[8] s[8] m[8] */
#define S_RED  46304    /* [32] */
#define S_MU   46336    /* [8] */
#define S_RS   46344    /* [8] */
#define SMEM_FLOATS 46352
// prologue overlay: sX [0,1024) + wtile [1024,14848) inside S_TEM

// ---------------- device globals ----------------
__device__ float    g_wx[T_STEPS * BB * H3];
__device__ float    g_whbuf[2][BB * H3];
__device__ unsigned g_lineA[NBLK][32];    // [0]=flag (128B padded)
__device__ unsigned g_lineB[NSCAL][32];   // [0]=flag, [1]=value bits
__device__ unsigned g_epochA;

// ---------------- helpers ----------------
__device__ __forceinline__ unsigned ld_acq(const unsigned* p) {
    unsigned v;
    asm volatile("ld.global.acquire.gpu.b32 %0, [%1];" : "=r"(v) : "l"(p) : "memory");
    return v;
}
__device__ __forceinline__ void st_rel(unsigned* p, unsigned v) {
    asm volatile("st.global.release.gpu.b32 [%0], %1;" :: "l"(p), "r"(v) : "memory");
}
__device__ __forceinline__ float sigm(float x) { return 1.f / (1.f + __expf(-x)); }
__device__ __forceinline__ float dot4(float4 a, float4 b) {
    return fmaf(a.x, b.x, fmaf(a.y, b.y, fmaf(a.z, b.z, a.w * b.w)));
}
__device__ __forceinline__ float wred(float v) {
#pragma unroll
    for (int o = 16; o; o >>= 1) v += __shfl_down_sync(0xffffffffu, v, o);
    return v;
}
__device__ __forceinline__ float wxor(float v) {
#pragma unroll
    for (int o = 16; o; o >>= 1) v += __shfl_xor_sync(0xffffffffu, v, o);
    return v;
}
__device__ __forceinline__ void block_sum2(float& a, float& b, float* sRed) {
#pragma unroll
    for (int o = 16; o; o >>= 1) {
        a += __shfl_down_sync(0xffffffffu, a, o);
        b += __shfl_down_sync(0xffffffffu, b, o);
    }
    __syncthreads();
    const int w = threadIdx.x >> 5;
    if ((threadIdx.x & 31) == 0) { sRed[w] = a; sRed[16 + w] = b; }
    __syncthreads();
    float ra = 0.f, rb = 0.f;
#pragma unroll
    for (int i = 0; i < 16; i++) { ra += sRed[i]; rb += sRed[16 + i]; }
    a = ra; b = rb;
}

__global__ void zero_flags_kernel() {
    int t = threadIdx.x;
    if (t < NBLK)  g_lineA[t][0] = 0u;
    if (t < NSCAL) g_lineB[t][0] = 0u;
    if (t == 0)    g_epochA = 0u;
}

// ====================================================================
__global__ void __launch_bounds__(NTHR, 1)
sgru_main(const float* __restrict__ x,       const float* __restrict__ h_in,
          const float* __restrict__ v_in,    const float* __restrict__ dU_in,
          const float* __restrict__ te_in,   const float* __restrict__ tE_in,
          const float* __restrict__ x2h_w,   const float* __restrict__ x2h_b,
          const float* __restrict__ h2h_w,   const float* __restrict__ h2h_b,
          const float* __restrict__ lnx_g,   const float* __restrict__ lnx_b,
          const float* __restrict__ lnh_g,   const float* __restrict__ lnh_b,
          const float* __restrict__ h2mod_w, const float* __restrict__ h2mod_b,
          const float* __restrict__ m2r_w,   const float* __restrict__ m2r_b,
          const float* __restrict__ m2s_w,   const float* __restrict__ m2s_b,
          const float* __restrict__ m2m_w,   const float* __restrict__ m2m_b,
          const float* __restrict__ alpha_p, const float* __restrict__ tauU_p,
          float* __restrict__ out)
{
    extern __shared__ float sm[];
    const int tid = threadIdx.x;
    const int bk  = blockIdx.x;
    const int wid = tid >> 5, lid = tid & 31;
    const int i0  = bk * 4;
    const int g   = tid >> 7;        // il group 0..3
    const int q   = tid & 127;       // quad index
    const int i   = i0 + g;

    float*  sWh   = sm + S_WH;
    float*  sH    = sm + S_H;
    float*  sHfw  = sm + S_HFW;
    float*  sTe   = sm + S_TE;
    float*  sZW   = sm + S_ZW;
    float*  sFwP  = sm + S_FWP;
    float*  sMod  = sm + S_MOD;
    float*  sScal = sm + S_SCAL;
    float*  sRed  = sm + S_RED;
    float*  sMu   = sm + S_MU;
    float*  sRs   = sm + S_RS;
    float4* sTE4  = (float4*)(sm + S_TEM);
    float4* sH4   = (float4*)sH;
    float4* sHfw4 = (float4*)sHfw;
    float4* sTe4  = (float4*)sTe;

    const float spa     = log1pf(expf(alpha_p[0]));
    const float inv_spe = 1.f / (spa + 1e-8f);
    const float tau     = 1.f / (1.f + expf(-tauU_p[0]));
    const float omtau   = 1.f - tau;

    // zo row base for this block (blocks 24..127 own 10 rows each)
    const int zbase = (bk - 24) * 10;

    // ================= PROLOGUE A: g_wx = LN(x @ x2h^T + b) =================
    {
        float* sX    = sm;           // [4][256]
        float* wtile = sm + 1024;    // [1536][9]
        const int rg0 = bk * 4;

        float acc[4][3];
#pragma unroll
        for (int r = 0; r < 4; r++)
#pragma unroll
            for (int p = 0; p < 3; p++) acc[r][p] = 0.f;

        for (int idx = tid; idx < 4 * IN_DIM; idx += NTHR)
            sX[idx] = x[(size_t)rg0 * IN_DIM + idx];

        for (int ct = 0; ct < 32; ++ct) {
            const int c0 = ct * 8;
            __syncthreads();
            for (int idx = tid; idx < H3 * 8; idx += NTHR) {
                int kl = idx >> 3, c = idx & 7;
                wtile[kl * 9 + c] = x2h_w[(size_t)kl * IN_DIM + c0 + c];
            }
            __syncthreads();
            float xv[4][8];
#pragma unroll
            for (int r = 0; r < 4; r++)
#pragma unroll
                for (int c = 0; c < 8; c++) xv[r][c] = sX[r * IN_DIM + c0 + c];
#pragma unroll
            for (int p = 0; p < 3; p++) {
                const int kk = tid + NTHR * p;
                float wv[8];
#pragma unroll
                for (int c = 0; c < 8; c++) wv[c] = wtile[kk * 9 + c];
#pragma unroll
                for (int r = 0; r < 4; r++)
#pragma unroll
                    for (int c = 0; c < 8; c++)
                        acc[r][p] = fmaf(wv[c], xv[r][c], acc[r][p]);
            }
        }
#pragma unroll
        for (int p = 0; p < 3; p++) {
            const float bq = x2h_b[tid + NTHR * p];
#pragma unroll
            for (int r = 0; r < 4; r++) acc[r][p] += bq;
        }
#pragma unroll
        for (int r = 0; r < 4; r++) {
            float s1 = 0.f, s2 = 0.f;
#pragma unroll
            for (int p = 0; p < 3; p++) { float v = acc[r][p]; s1 += v; s2 = fmaf(v, v, s2); }
            block_sum2(s1, s2, sRed);
            const float mu   = s1 * (1.f / H3);
            const float rstd = rsqrtf(s2 * (1.f / H3) - mu * mu + 1e-5f);
            float* wrow = g_wx + (size_t)(rg0 + r) * H3;
#pragma unroll
            for (int p = 0; p < 3; p++) {
                const int kk = tid + NTHR * p;
                wrow[kk] = (acc[r][p] - mu) * rstd * lnx_g[kk] + lnx_b[kk];
            }
        }
        __syncthreads();
    }

    // ================= PROLOGUE B: persistent state =================
    float4 rDU4[8], w4, up4, lo4;
    float vr[8];
    {
        w4 = ((const float4*)(h2h_w + (size_t)(2 * HH + i) * HH))[q];
        up4.x =  fmaxf(1.f - w4.x, 0.f) * inv_spe;  lo4.x = -fmaxf(1.f + w4.x, 0.f) * inv_spe;
        up4.y =  fmaxf(1.f - w4.y, 0.f) * inv_spe;  lo4.y = -fmaxf(1.f + w4.y, 0.f) * inv_spe;
        up4.z =  fmaxf(1.f - w4.z, 0.f) * inv_spe;  lo4.z = -fmaxf(1.f + w4.z, 0.f) * inv_spe;
        up4.w =  fmaxf(1.f - w4.w, 0.f) * inv_spe;  lo4.w = -fmaxf(1.f + w4.w, 0.f) * inv_spe;
#pragma unroll
        for (int b = 0; b < 8; b++) {
            const size_t g4 = (size_t)(b * HH + i) * 128 + q;
            rDU4[b] = ((const float4*)dU_in)[g4];
            sTE4[(g * 8 + b) * 128 + q] = ((const float4*)tE_in)[g4];
        }
        if (bk >= 24) {
            for (int idx = tid; idx < 10 * HH; idx += NTHR) {
                const int w = idx >> 9, j = idx & 511;
                const int k = zbase + w;
                if (k < 1024)
                    sZW[idx] = h2h_w[(size_t)k * HH + j];
            }
        }
#pragma unroll
        for (int b = 0; b < 8; b++) {
            vr[b] = v_in[b * HH + tid];
            sTe[b * HH + tid] = te_in[b * HH + tid];
            sH [b * HH + tid] = h_in[b * HH + tid];
        }
        __syncthreads();
    }

    // ================= MAIN LOOP =================
    for (int it = 0; it <= T_STEPS; ++it) {
        const bool last = (it == T_STEPS);
        float* whb = g_whbuf[it & 1];

        // ---- zo GEMM: blocks >=24, warps 0..9, one row each ----
        if (!last && bk >= 24 && wid < 10) {
            const int k = zbase + wid;
            if (k < 1024) {
                float accA[8];
#pragma unroll
                for (int b = 0; b < 8; b++) accA[b] = 0.f;
#pragma unroll
                for (int c = 0; c < 4; c++) {
                    const float4 wv = ((const float4*)&sZW[wid * HH])[lid + 32 * c];
#pragma unroll
                    for (int b = 0; b < 8; b++)
                        accA[b] += dot4(wv, sH4[b * 128 + lid + 32 * c]);
                }
                const float bias = h2h_b[k];
#pragma unroll
                for (int b = 0; b < 8; b++) {
                    float v = wxor(accA[b]);
                    if (lid == b) __stcg(&whb[b * H3 + k], v + bias);
                }
            }
        }

        // ---- wait scalars (24 lines) ----
        if (it > 0) {
            for (;;) {
                int ok = 1;
                if (tid < NSCAL) ok = (ld_acq(&g_lineB[tid][0]) >= (unsigned)it);
                if (__syncthreads_count(ok) == NTHR) break;
            }
            if (tid < NSCAL) {
                const int b = tid & 7, sc = tid >> 3;
                sScal[sc * 8 + b] = __ldcg((const float*)&g_lineB[tid][1]);
            }
            __syncthreads();
        }

        // ---- trace update (step it-1) + fused dv partials ----
        float tnew[8];
#pragma unroll
        for (int b = 0; b < 8; b++) {
            if (it > 0) {
                const float rb  = sScal[b];
                const float sb  = sScal[8 + b];
                const float mb  = sScal[16 + b];
                const float oms = 1.f - sb;
                const float tm  = tau * mb;
                const float hfi = sHfw[b * HH + i];
                const float tei = sTe [b * HH + i];
                const float4 teo4 = sTe4 [b * 128 + q];
                const float4 hf4  = sHfw4[b * 128 + q];
                float4 t4 = sTE4[(g * 8 + b) * 128 + q];
                t4.x = oms * t4.x + sb * (hfi * teo4.x - tei * hf4.x);
                t4.y = oms * t4.y + sb * (hfi * teo4.y - tei * hf4.y);
                t4.z = oms * t4.z + sb * (hfi * teo4.z - tei * hf4.z);
                t4.w = oms * t4.w + sb * (hfi * teo4.w - tei * hf4.w);
                sTE4[(g * 8 + b) * 128 + q] = t4;
                float4 d4 = rDU4[b];
                d4.x = fmaxf(fminf(omtau * d4.x + tm * t4.x, up4.x), lo4.x);
                d4.y = fmaxf(fminf(omtau * d4.y + tm * t4.y, up4.y), lo4.y);
                d4.z = fmaxf(fminf(omtau * d4.z + tm * t4.z, up4.z), lo4.z);
                d4.w = fmaxf(fminf(omtau * d4.w + tm * t4.w, up4.w), lo4.w);
                rDU4[b] = d4;
                tnew[b] = (1.f - rb) * sTe[b * HH + tid] + rb * sHfw[b * HH + tid];
            }
            if (!last) {
                const float4 h4 = sH4[b * 128 + q];
                const float4 d4 = rDU4[b];
                float p = (w4.x + spa * d4.x) * h4.x;
                p = fmaf(w4.y + spa * d4.y, h4.y, p);
                p = fmaf(w4.z + spa * d4.z, h4.z, p);
                p = fmaf(w4.w + spa * d4.w, h4.w, p);
                p = wred(p);
                if (lid == 0) sFwP[(g * 8 + b) * 4 + (wid & 3)] = p;
            }
        }
        __syncthreads();
        if (it > 0) {
#pragma unroll
            for (int b = 0; b < 8; b++) sTe[b * HH + tid] = tnew[b];
        }

        if (last) break;

        // ---- dv combine + publish flagA ----
        if (tid < 32) {
            const float v = sFwP[tid * 4] + sFwP[tid * 4 + 1] + sFwP[tid * 4 + 2] + sFwP[tid * 4 + 3];
            const int b = tid & 7, gg = tid >> 3;
            const int k = 2 * HH + i0 + gg;
            __stcg(&whb[b * H3 + k], v + h2h_b[k]);
        }
        __syncthreads();
        if (tid == 0) st_rel(&g_lineA[bk][0], (unsigned)(it + 1));

        // ---- aggregator hop (block 0, publishes flagA earliest) ----
        if (bk == AGG) {
            for (;;) {
                int ok = 1;
                if (tid < NBLK) ok = (ld_acq(&g_lineA[tid][0]) >= (unsigned)(it + 1));
                if (__syncthreads_count(ok) == NTHR) break;
            }
            if (tid == 0) st_rel(&g_epochA, (unsigned)(it + 1));
        }
        // shadow: dUs(it-1) store
        if (it > 0) {
            float4* dus4 = (float4*)(out + OUT_DUS + (size_t)(it - 1) * (BB * HH * HH));
#pragma unroll
            for (int b = 0; b < 8; b++)
                __stcs(&dus4[(size_t)(b * HH + i) * 128 + q], rDU4[b]);
        }
        // wait epoch
        if (tid == 0) { while (ld_acq(&g_epochA) < (unsigned)(it + 1)) {} }
        __syncthreads();

        // ---- Wh load fused with LN stats ----
        {
            const int b = tid >> 6, l6 = tid & 63;
            float s1 = 0.f, s2 = 0.f;
#pragma unroll
            for (int p = 0; p < 24; p++) {
                const float v = __ldcg(&whb[b * H3 + l6 + 64 * p]);
                sWh[b * H3 + l6 + 64 * p] = v;
                s1 += v; s2 = fmaf(v, v, s2);
            }
#pragma unroll
            for (int o = 16; o; o >>= 1) {
                s1 += __shfl_down_sync(0xffffffffu, s1, o);
                s2 += __shfl_down_sync(0xffffffffu, s2, o);
            }
            if (lid == 0) { sRed[wid * 2] = s1; sRed[wid * 2 + 1] = s2; }
            __syncthreads();
            if (tid < 8) {
                const float t1 = sRed[tid * 4] + sRed[tid * 4 + 2];
                const float t2 = sRed[tid * 4 + 1] + sRed[tid * 4 + 3];
                const float mu = t1 * (1.f / H3);
                sMu[tid] = mu;
                sRs[tid] = rsqrtf(t2 * (1.f / H3) - mu * mu + 1e-5f);
            }
            __syncthreads();
        }

        // ---- gates (redundant across blocks) ----
        {
            const float lg0 = lnh_g[tid],          lb0 = lnh_b[tid];
            const float lg1 = lnh_g[HH + tid],     lb1 = lnh_b[HH + tid];
            const float lg2 = lnh_g[2 * HH + tid], lb2 = lnh_b[2 * HH + tid];
            const float* wxg = g_wx + (size_t)it * (BB * H3);
#pragma unroll
            for (int b = 0; b < 8; b++) {
                const float mu = sMu[b], rs = sRs[b];
                const float wx0 = __ldcg(&wxg[b * H3 + tid]);
                const float wx1 = __ldcg(&wxg[b * H3 + HH + tid]);
                const float wx2 = __ldcg(&wxg[b * H3 + 2 * HH + tid]);
                const float pz = (sWh[b * H3 + tid]          - mu) * rs * lg0 + lb0 + wx0;
                const float po = (sWh[b * H3 + HH + tid]     - mu) * rs * lg1 + lb1 + wx1;
                const float pd = (sWh[b * H3 + 2 * HH + tid] - mu) * rs * lg2 + lb2 + wx2;
                const float z = sigm(pz);
                const float o = sigm(po);
                vr[b] = (1.f - z) * vr[b] + z * pd;
                const float nh = fmaxf(vr[b], 0.f);
                const float hf = o * nh;
                sH  [b * HH + tid] = nh;
                sHfw[b * HH + tid] = hf;
                if (bk == 32 + b)
                    out[OUT_OUTS + (size_t)it * (BB * HH) + b * HH + tid] = nh;
            }
        }
        __syncthreads();

        // ---- scalar blocks (0..23): 32 mod rows + one scalar each ----
        if (bk < NSCAL) {
            const int b  = bk & 7;
            const int sc = bk >> 3;        // 0=r, 1=s, 2=m
            const int r0 = sc * 32;
#pragma unroll
            for (int rr = 0; rr < 2; rr++) {
                const int rl  = wid * 2 + rr;
                const int row = r0 + rl;
                const float4* mw = (const float4*)(h2mod_w + (size_t)row * HH);
                float a = 0.f;
#pragma unroll
                for (int c = 0; c < 4; c++)
                    a += dot4(mw[lid + 32 * c], sH4[b * 128 + lid + 32 * c]);
                a = wxor(a);
                if (lid == 0) {
                    const float mv = fmaxf(a + h2mod_b[row], 0.f);
                    sMod[rl] = mv;
                    out[OUT_MODS + (size_t)it * (BB * 96) + b * 96 + row] = mv;
                }
            }
            __syncthreads();
            if (wid == 0) {
                const float* ww = (sc == 0) ? m2r_w : (sc == 1) ? m2s_w : m2m_w;
                float a = wxor(sMod[lid] * ww[lid]);
                if (lid == 0) {
                    float val;
                    if (sc == 0) {
                        val = sigm(a + m2r_b[0]);
                        out[OUT_RS + (size_t)it * BB + b] = val;
                    } else if (sc == 1) {
                        val = sigm(a + m2s_b[0]);
                        out[OUT_SS + (size_t)it * BB + b] = val;
                    } else {
                        const float mm = a + m2m_b[0];
                        val = mm - tanhf(mm);
                        out[OUT_MS + (size_t)it * BB + b] = val;
                    }
                    __stcg((float*)&g_lineB[bk][1], val);
                    st_rel(&g_lineB[bk][0], (unsigned)(it + 1));
                }
            }
        }
    }

    // ================= EPILOGUE =================
    {
        float4* dus4 = (float4*)(out + OUT_DUS + (size_t)(T_STEPS - 1) * (BB * HH * HH));
        float4* duf4 = (float4*)(out + OUT_DUF);
        float4* tem4 = (float4*)(out + OUT_TEMAT);
#pragma unroll
        for (int b = 0; b < 8; b++) {
            const size_t g4 = (size_t)(b * HH + i) * 128 + q;
            dus4[g4] = rDU4[b];
            duf4[g4] = rDU4[b];
            tem4[g4] = sTE4[(g * 8 + b) * 128 + q];
        }
    }
    if (bk < BB) {
        out[OUT_V   + bk * HH + tid] = vr[bk];
        out[OUT_H   + bk * HH + tid] = sH[bk * HH + tid];
        out[OUT_TEF + bk * HH + tid] = sTe[bk * HH + tid];
    }
}

// ====================================================================
extern "C" void kernel_launch(void* const* d_in, const int* in_sizes, int n_in,
                              void* d_out, int out_size) {
    const float* x       = (const float*)d_in[0];
    const float* h       = (const float*)d_in[1];
    const float* v       = (const float*)d_in[2];
    const float* dU      = (const float*)d_in[3];
    const float* te      = (const float*)d_in[4];
    const float* tE      = (const float*)d_in[5];
    const float* x2h_w   = (const float*)d_in[6];
    const float* x2h_b   = (const float*)d_in[7];
    const float* h2h_w   = (const float*)d_in[8];
    const float* h2h_b   = (const float*)d_in[9];
    const float* lnx_g   = (const float*)d_in[10];
    const float* lnx_b   = (const float*)d_in[11];
    const float* lnh_g   = (const float*)d_in[12];
    const float* lnh_b   = (const float*)d_in[13];
    const float* h2mod_w = (const float*)d_in[14];
    const float* h2mod_b = (const float*)d_in[15];
    const float* m2r_w   = (const float*)d_in[16];
    const float* m2r_b   = (const float*)d_in[17];
    const float* m2s_w   = (const float*)d_in[18];
    const float* m2s_b   = (const float*)d_in[19];
    const float* m2m_w   = (const float*)d_in[20];
    const float* m2m_b   = (const float*)d_in[21];
    const float* alpha   = (const float*)d_in[22];
    const float* tauU    = (const float*)d_in[23];
    float* out = (float*)d_out;

    const size_t smem = (size_t)SMEM_FLOATS * sizeof(float);
    cudaFuncSetAttribute(sgru_main, cudaFuncAttributeMaxDynamicSharedMemorySize, (int)smem);

    zero_flags_kernel<<<1, 128>>>();
    sgru_main<<<NBLK, NTHR, smem>>>(x, h, v, dU, te, tE,
                                    x2h_w, x2h_b, h2h_w, h2h_b,
                                    lnx_g, lnx_b, lnh_g, lnh_b,
                                    h2mod_w, h2mod_b,
                                    m2r_w, m2r_b, m2s_w, m2s_b, m2m_w, m2m_b,
                                    alpha, tauU, out);
}

// round 9
// speedup vs baseline: 1.6143x; 1.4448x over previous
#include <cuda_runtime.h>
#include <cstdint>

#define T_STEPS 64
#define BB      8
#define IN_DIM  256
#define HH      512
#define H3      1536
#define NBLK    128
#define NTHR    512
#define AGG     127

// ---------------- output offsets (floats) ----------------
#define OUT_V      0ull
#define OUT_H      4096ull
#define OUT_DUF    8192ull
#define OUT_TEF    2105344ull
#define OUT_TEMAT  2109440ull
#define OUT_OUTS   4206592ull
#define OUT_DUS    4468736ull
#define OUT_MODS   138686464ull
#define OUT_SS     138735616ull
#define OUT_MS     138736128ull
#define OUT_RS     138736640ull

// ---------------- smem layout (float index) ----------------
#define S_TEM  0        /* [32][512] trace_E matrix */
#define S_H    16384    /* [8][512] */
#define S_HFW  20480    /* [8][512] */
#define S_TE   24576    /* [8][512] */
#define S_ZW   28672    /* [8][512] zo weight rows */
#define S_NH   32768    /* [512] gate-block new_h */
#define S_FWP  33280    /* [32][4] */
#define S_MOD  33408    /* [96] pad 128 */
#define S_SCAL 33536    /* r[8] s[8] m[8] */
#define S_RED  33568    /* [32] */
#define SMEM_FLOATS 33600
// prologue overlay: sX [0,1024) + wtile [1024,14848) inside S_TEM

// ---------------- device globals ----------------
__device__ float    g_wx[T_STEPS * BB * H3];
__device__ float    g_whbuf[2][BB * H3];
__device__ float    g_h[BB * HH];
__device__ float    g_hfw[BB * HH];
__device__ unsigned g_lineA[NBLK][32];   // [0]=flag (128B padded)
__device__ unsigned g_lineH[BB][32];     // [0]=flag (h/hfw ready)
__device__ unsigned g_lineB[BB][32];     // [0]=flag, [1]=r, [2]=s, [3]=m
__device__ unsigned g_epochA;

// ---------------- helpers ----------------
__device__ __forceinline__ unsigned ld_acq(const unsigned* p) {
    unsigned v;
    asm volatile("ld.global.acquire.gpu.b32 %0, [%1];" : "=r"(v) : "l"(p) : "memory");
    return v;
}
__device__ __forceinline__ void st_rel(unsigned* p, unsigned v) {
    asm volatile("st.global.release.gpu.b32 [%0], %1;" :: "l"(p), "r"(v) : "memory");
}
__device__ __forceinline__ float sigm(float x) { return 1.f / (1.f + __expf(-x)); }
__device__ __forceinline__ float dot4(float4 a, float4 b) {
    return fmaf(a.x, b.x, fmaf(a.y, b.y, fmaf(a.z, b.z, a.w * b.w)));
}
__device__ __forceinline__ float wred(float v) {
#pragma unroll
    for (int o = 16; o; o >>= 1) v += __shfl_down_sync(0xffffffffu, v, o);
    return v;
}
__device__ __forceinline__ float wxor(float v) {
#pragma unroll
    for (int o = 16; o; o >>= 1) v += __shfl_xor_sync(0xffffffffu, v, o);
    return v;
}
__device__ __forceinline__ void block_sum2(float& a, float& b, float* sRed) {
#pragma unroll
    for (int o = 16; o; o >>= 1) {
        a += __shfl_down_sync(0xffffffffu, a, o);
        b += __shfl_down_sync(0xffffffffu, b, o);
    }
    __syncthreads();
    const int w = threadIdx.x >> 5;
    if ((threadIdx.x & 31) == 0) { sRed[w] = a; sRed[16 + w] = b; }
    __syncthreads();
    float ra = 0.f, rb = 0.f;
#pragma unroll
    for (int i = 0; i < 16; i++) { ra += sRed[i]; rb += sRed[16 + i]; }
    a = ra; b = rb;
}

__global__ void zero_flags_kernel() {
    int t = threadIdx.x;
    if (t < NBLK) g_lineA[t][0] = 0u;
    if (t < BB) { g_lineH[t][0] = 0u; g_lineB[t][0] = 0u; }
    if (t == 0)  g_epochA = 0u;
}

// ====================================================================
__global__ void __launch_bounds__(NTHR, 1)
sgru_main(const float* __restrict__ x,       const float* __restrict__ h_in,
          const float* __restrict__ v_in,    const float* __restrict__ dU_in,
          const float* __restrict__ te_in,   const float* __restrict__ tE_in,
          const float* __restrict__ x2h_w,   const float* __restrict__ x2h_b,
          const float* __restrict__ h2h_w,   const float* __restrict__ h2h_b,
          const float* __restrict__ lnx_g,   const float* __restrict__ lnx_b,
          const float* __restrict__ lnh_g,   const float* __restrict__ lnh_b,
          const float* __restrict__ h2mod_w, const float* __restrict__ h2mod_b,
          const float* __restrict__ m2r_w,   const float* __restrict__ m2r_b,
          const float* __restrict__ m2s_w,   const float* __restrict__ m2s_b,
          const float* __restrict__ m2m_w,   const float* __restrict__ m2m_b,
          const float* __restrict__ alpha_p, const float* __restrict__ tauU_p,
          float* __restrict__ out)
{
    extern __shared__ float sm[];
    const int tid = threadIdx.x;
    const int bk  = blockIdx.x;
    const int wid = tid >> 5, lid = tid & 31;
    const int i0  = bk * 4;
    const int g   = tid >> 7;        // il group 0..3
    const int q   = tid & 127;       // quad index
    const int i   = i0 + g;

    float*  sH    = sm + S_H;
    float*  sHfw  = sm + S_HFW;
    float*  sTe   = sm + S_TE;
    float*  sZW   = sm + S_ZW;
    float*  sNH   = sm + S_NH;
    float*  sFwP  = sm + S_FWP;
    float*  sMod  = sm + S_MOD;
    float*  sScal = sm + S_SCAL;
    float*  sRed  = sm + S_RED;
    float4* sTE4  = (float4*)(sm + S_TEM);
    float4* sH4   = (float4*)sH;
    float4* sHfw4 = (float4*)sHfw;
    float4* sTe4  = (float4*)sTe;

    const float spa     = log1pf(expf(alpha_p[0]));
    const float inv_spe = 1.f / (spa + 1e-8f);
    const float tau     = 1.f / (1.f + expf(-tauU_p[0]));
    const float omtau   = 1.f - tau;

    // ================= PROLOGUE A: g_wx = LN(x @ x2h^T + b) =================
    {
        float* sX    = sm;           // [4][256]
        float* wtile = sm + 1024;    // [1536][9]
        const int rg0 = bk * 4;

        float acc[4][3];
#pragma unroll
        for (int r = 0; r < 4; r++)
#pragma unroll
            for (int p = 0; p < 3; p++) acc[r][p] = 0.f;

        for (int idx = tid; idx < 4 * IN_DIM; idx += NTHR)
            sX[idx] = x[(size_t)rg0 * IN_DIM + idx];

        for (int ct = 0; ct < 32; ++ct) {
            const int c0 = ct * 8;
            __syncthreads();
            for (int idx = tid; idx < H3 * 8; idx += NTHR) {
                int kl = idx >> 3, c = idx & 7;
                wtile[kl * 9 + c] = x2h_w[(size_t)kl * IN_DIM + c0 + c];
            }
            __syncthreads();
            float xv[4][8];
#pragma unroll
            for (int r = 0; r < 4; r++)
#pragma unroll
                for (int c = 0; c < 8; c++) xv[r][c] = sX[r * IN_DIM + c0 + c];
#pragma unroll
            for (int p = 0; p < 3; p++) {
                const int kk = tid + NTHR * p;
                float wv[8];
#pragma unroll
                for (int c = 0; c < 8; c++) wv[c] = wtile[kk * 9 + c];
#pragma unroll
                for (int r = 0; r < 4; r++)
#pragma unroll
                    for (int c = 0; c < 8; c++)
                        acc[r][p] = fmaf(wv[c], xv[r][c], acc[r][p]);
            }
        }
#pragma unroll
        for (int p = 0; p < 3; p++) {
            const float bq = x2h_b[tid + NTHR * p];
#pragma unroll
            for (int r = 0; r < 4; r++) acc[r][p] += bq;
        }
#pragma unroll
        for (int r = 0; r < 4; r++) {
            float s1 = 0.f, s2 = 0.f;
#pragma unroll
            for (int p = 0; p < 3; p++) { float v = acc[r][p]; s1 += v; s2 = fmaf(v, v, s2); }
            block_sum2(s1, s2, sRed);
            const float mu   = s1 * (1.f / H3);
            const float rstd = rsqrtf(s2 * (1.f / H3) - mu * mu + 1e-5f);
            float* wrow = g_wx + (size_t)(rg0 + r) * H3;
#pragma unroll
            for (int p = 0; p < 3; p++) {
                const int kk = tid + NTHR * p;
                wrow[kk] = (acc[r][p] - mu) * rstd * lnx_g[kk] + lnx_b[kk];
            }
        }
        __syncthreads();
    }

    // ================= PROLOGUE B: persistent state =================
    float4 rDU4[8], w4, up4, lo4;
    float vb = 0.f;
    {
        w4 = ((const float4*)(h2h_w + (size_t)(2 * HH + i) * HH))[q];
        up4.x =  fmaxf(1.f - w4.x, 0.f) * inv_spe;  lo4.x = -fmaxf(1.f + w4.x, 0.f) * inv_spe;
        up4.y =  fmaxf(1.f - w4.y, 0.f) * inv_spe;  lo4.y = -fmaxf(1.f + w4.y, 0.f) * inv_spe;
        up4.z =  fmaxf(1.f - w4.z, 0.f) * inv_spe;  lo4.z = -fmaxf(1.f + w4.z, 0.f) * inv_spe;
        up4.w =  fmaxf(1.f - w4.w, 0.f) * inv_spe;  lo4.w = -fmaxf(1.f + w4.w, 0.f) * inv_spe;
#pragma unroll
        for (int b = 0; b < 8; b++) {
            const size_t g4 = (size_t)(b * HH + i) * 128 + q;
            rDU4[b] = ((const float4*)dU_in)[g4];
            sTE4[(g * 8 + b) * 128 + q] = ((const float4*)tE_in)[g4];
        }
        for (int idx = tid; idx < 8 * HH; idx += NTHR) {
            const int w = idx >> 9, j = idx & 511;
            sZW[idx] = h2h_w[(size_t)(bk * 8 + w) * HH + j];
        }
#pragma unroll
        for (int b = 0; b < 8; b++) {
            sTe[b * HH + tid] = te_in[b * HH + tid];
            sH [b * HH + tid] = h_in[b * HH + tid];
        }
        if (bk < BB) vb = v_in[bk * HH + tid];
        __syncthreads();
    }

    // ================= MAIN LOOP =================
    for (int it = 0; it <= T_STEPS; ++it) {
        const bool last = (it == T_STEPS);
        float* whb = g_whbuf[it & 1];

        // ---- wait flagH, load h/hfw ----
        if (it > 0) {
            for (;;) {
                int ok = 1;
                if (tid < BB) ok = (ld_acq(&g_lineH[tid][0]) >= (unsigned)it);
                if (__syncthreads_count(ok) == NTHR) break;
            }
            const float4* gh4 = (const float4*)g_h;
            const float4* gf4 = (const float4*)g_hfw;
#pragma unroll
            for (int p = 0; p < 2; p++) {
                sH4  [tid + NTHR * p] = __ldcg(&gh4[tid + NTHR * p]);
                sHfw4[tid + NTHR * p] = __ldcg(&gf4[tid + NTHR * p]);
            }
            __syncthreads();
        }

        // ---- zo GEMM (warps 0..7), overlaps gate blocks' mod/scalar tail ----
        if (!last && wid < 8) {
            const int k = bk * 8 + wid;
            float accA[8];
#pragma unroll
            for (int b = 0; b < 8; b++) accA[b] = 0.f;
#pragma unroll
            for (int c = 0; c < 4; c++) {
                const float4 wv = ((const float4*)&sZW[wid * HH])[lid + 32 * c];
#pragma unroll
                for (int b = 0; b < 8; b++)
                    accA[b] += dot4(wv, sH4[b * 128 + lid + 32 * c]);
            }
            const float bias = h2h_b[k];
#pragma unroll
            for (int b = 0; b < 8; b++) {
                float v = wxor(accA[b]);
                if (lid == b) __stcg(&whb[b * H3 + k], v + bias);
            }
        }

        // ---- wait flagB (scalars) ----
        if (it > 0) {
            for (;;) {
                int ok = 1;
                if (tid < BB) ok = (ld_acq(&g_lineB[tid][0]) >= (unsigned)it);
                if (__syncthreads_count(ok) == NTHR) break;
            }
            if (tid < BB) {
                sScal[tid]      = __ldcg((const float*)&g_lineB[tid][1]);
                sScal[8 + tid]  = __ldcg((const float*)&g_lineB[tid][2]);
                sScal[16 + tid] = __ldcg((const float*)&g_lineB[tid][3]);
            }
            __syncthreads();
        }

        // ---- trace update (step it-1) + fused dv partials ----
        float tnew[8];
#pragma unroll
        for (int b = 0; b < 8; b++) {
            if (it > 0) {
                const float rb  = sScal[b];
                const float sb  = sScal[8 + b];
                const float mb  = sScal[16 + b];
                const float oms = 1.f - sb;
                const float tm  = tau * mb;
                const float hfi = sHfw[b * HH + i];
                const float tei = sTe [b * HH + i];
                const float4 teo4 = sTe4 [b * 128 + q];
                const float4 hf4  = sHfw4[b * 128 + q];
                float4 t4 = sTE4[(g * 8 + b) * 128 + q];
                t4.x = oms * t4.x + sb * (hfi * teo4.x - tei * hf4.x);
                t4.y = oms * t4.y + sb * (hfi * teo4.y - tei * hf4.y);
                t4.z = oms * t4.z + sb * (hfi * teo4.z - tei * hf4.z);
                t4.w = oms * t4.w + sb * (hfi * teo4.w - tei * hf4.w);
                sTE4[(g * 8 + b) * 128 + q] = t4;
                float4 d4 = rDU4[b];
                d4.x = fmaxf(fminf(omtau * d4.x + tm * t4.x, up4.x), lo4.x);
                d4.y = fmaxf(fminf(omtau * d4.y + tm * t4.y, up4.y), lo4.y);
                d4.z = fmaxf(fminf(omtau * d4.z + tm * t4.z, up4.z), lo4.z);
                d4.w = fmaxf(fminf(omtau * d4.w + tm * t4.w, up4.w), lo4.w);
                rDU4[b] = d4;
                tnew[b] = (1.f - rb) * sTe[b * HH + tid] + rb * sHfw[b * HH + tid];
            }
            if (!last) {
                const float4 h4 = sH4[b * 128 + q];
                const float4 d4 = rDU4[b];
                float p = (w4.x + spa * d4.x) * h4.x;
                p = fmaf(w4.y + spa * d4.y, h4.y, p);
                p = fmaf(w4.z + spa * d4.z, h4.z, p);
                p = fmaf(w4.w + spa * d4.w, h4.w, p);
                p = wred(p);
                if (lid == 0) sFwP[(g * 8 + b) * 4 + (wid & 3)] = p;
            }
        }
        __syncthreads();
        if (it > 0) {
#pragma unroll
            for (int b = 0; b < 8; b++) sTe[b * HH + tid] = tnew[b];
        }

        if (last) break;

        // ---- dv combine + publish flagA ----
        if (tid < 32) {
            const float v = sFwP[tid * 4] + sFwP[tid * 4 + 1] + sFwP[tid * 4 + 2] + sFwP[tid * 4 + 3];
            const int b = tid & 7, gg = tid >> 3;
            const int k = 2 * HH + i0 + gg;
            __stcg(&whb[b * H3 + k], v + h2h_b[k]);
        }
        __syncthreads();
        if (tid == 0) st_rel(&g_lineA[bk][0], (unsigned)(it + 1));

        // ---- aggregator hop (non-gate block) ----
        if (bk == AGG) {
            for (;;) {
                int ok = 1;
                if (tid < NBLK) ok = (ld_acq(&g_lineA[tid][0]) >= (unsigned)(it + 1));
                if (__syncthreads_count(ok) == NTHR) break;
            }
            if (tid == 0) st_rel(&g_epochA, (unsigned)(it + 1));
        }
        // shadow: dUs(it-1) store
        if (it > 0) {
            float4* dus4 = (float4*)(out + OUT_DUS + (size_t)(it - 1) * (BB * HH * HH));
#pragma unroll
            for (int b = 0; b < 8; b++)
                __stcs(&dus4[(size_t)(b * HH + i) * 128 + q], rDU4[b]);
        }
        // wait epoch
        if (tid == 0) { while (ld_acq(&g_epochA) < (unsigned)(it + 1)) {} }
        __syncthreads();

        // ---- gate blocks: LN + gates -> publish h/hfw (flagH), then mod + scalars (flagB) ----
        if (bk < BB) {
            const int b = bk;
            const float* whrow = whb + b * H3;
            const float p0 = __ldcg(&whrow[tid]);
            const float p1 = __ldcg(&whrow[HH + tid]);
            const float p2 = __ldcg(&whrow[2 * HH + tid]);
            float s1 = p0 + p1 + p2;
            float s2 = fmaf(p0, p0, fmaf(p1, p1, p2 * p2));
            block_sum2(s1, s2, sRed);
            const float mu = s1 * (1.f / H3);
            const float rs = rsqrtf(s2 * (1.f / H3) - mu * mu + 1e-5f);
            const float* wxg = g_wx + (size_t)it * (BB * H3) + b * H3;
            const float pz = (p0 - mu) * rs * lnh_g[tid]          + lnh_b[tid]          + __ldcg(&wxg[tid]);
            const float po = (p1 - mu) * rs * lnh_g[HH + tid]     + lnh_b[HH + tid]     + __ldcg(&wxg[HH + tid]);
            const float pd = (p2 - mu) * rs * lnh_g[2 * HH + tid] + lnh_b[2 * HH + tid] + __ldcg(&wxg[2 * HH + tid]);
            const float z = sigm(pz);
            const float o = sigm(po);
            vb = (1.f - z) * vb + z * pd;
            const float nh = fmaxf(vb, 0.f);
            const float hf = o * nh;
            __stcg(&g_h[b * HH + tid], nh);
            __stcg(&g_hfw[b * HH + tid], hf);
            out[OUT_OUTS + (size_t)it * (BB * HH) + b * HH + tid] = nh;
            sNH[tid] = nh;
            __syncthreads();
            if (tid == 0) st_rel(&g_lineH[b][0], (unsigned)(it + 1));

            // mod = relu(new_h @ h2mod^T + b): 96 rows, 16 warps x 6 rows
            const float4* nh4 = (const float4*)sNH;
            float4 nv[4];
#pragma unroll
            for (int c = 0; c < 4; c++) nv[c] = nh4[lid + 32 * c];
#pragma unroll
            for (int rr = 0; rr < 6; rr++) {
                const int row = wid * 6 + rr;
                const float4* mw = (const float4*)(h2mod_w + (size_t)row * HH);
                float a = 0.f;
#pragma unroll
                for (int c = 0; c < 4; c++) a += dot4(__ldcg(&mw[lid + 32 * c]), nv[c]);
                a = wxor(a);
                if (lid == 0) {
                    const float mv = fmaxf(a + h2mod_b[row], 0.f);
                    sMod[row] = mv;
                    out[OUT_MODS + (size_t)it * (BB * 96) + b * 96 + row] = mv;
                }
            }
            __syncthreads();
            if (wid < 3) {
                const float* ww = (wid == 0) ? m2r_w : (wid == 1) ? m2s_w : m2m_w;
                const float bb0 = (wid == 0) ? m2r_b[0] : (wid == 1) ? m2s_b[0] : m2m_b[0];
                float a = wxor(sMod[wid * 32 + lid] * ww[lid]);
                if (lid == 0) {
                    float val;
                    if (wid == 0) {
                        val = sigm(a + bb0);
                        out[OUT_RS + (size_t)it * BB + b] = val;
                    } else if (wid == 1) {
                        val = sigm(a + bb0);
                        out[OUT_SS + (size_t)it * BB + b] = val;
                    } else {
                        const float mm = a + bb0;
                        val = mm - tanhf(mm);
                        out[OUT_MS + (size_t)it * BB + b] = val;
                    }
                    __stcg((float*)&g_lineB[b][1 + wid], val);
                }
            }
            __syncthreads();
            if (tid == 0) st_rel(&g_lineB[b][0], (unsigned)(it + 1));
        }
    }

    // ================= EPILOGUE =================
    {
        float4* dus4 = (float4*)(out + OUT_DUS + (size_t)(T_STEPS - 1) * (BB * HH * HH));
        float4* duf4 = (float4*)(out + OUT_DUF);
        float4* tem4 = (float4*)(out + OUT_TEMAT);
#pragma unroll
        for (int b = 0; b < 8; b++) {
            const size_t g4 = (size_t)(b * HH + i) * 128 + q;
            dus4[g4] = rDU4[b];
            duf4[g4] = rDU4[b];
            tem4[g4] = sTE4[(g * 8 + b) * 128 + q];
        }
    }
    if (bk < BB) {
        out[OUT_V   + bk * HH + tid] = vb;
        out[OUT_H   + bk * HH + tid] = sH[bk * HH + tid];
        out[OUT_TEF + bk * HH + tid] = sTe[bk * HH + tid];
    }
}

// ====================================================================
extern "C" void kernel_launch(void* const* d_in, const int* in_sizes, int n_in,
                              void* d_out, int out_size) {
    const float* x       = (const float*)d_in[0];
    const float* h       = (const float*)d_in[1];
    const float* v       = (const float*)d_in[2];
    const float* dU      = (const float*)d_in[3];
    const float* te      = (const float*)d_in[4];
    const float* tE      = (const float*)d_in[5];
    const float* x2h_w   = (const float*)d_in[6];
    const float* x2h_b   = (const float*)d_in[7];
    const float* h2h_w   = (const float*)d_in[8];
    const float* h2h_b   = (const float*)d_in[9];
    const float* lnx_g   = (const float*)d_in[10];
    const float* lnx_b   = (const float*)d_in[11];
    const float* lnh_g   = (const float*)d_in[12];
    const float* lnh_b   = (const float*)d_in[13];
    const float* h2mod_w = (const float*)d_in[14];
    const float* h2mod_b = (const float*)d_in[15];
    const float* m2r_w   = (const float*)d_in[16];
    const float* m2r_b   = (const float*)d_in[17];
    const float* m2s_w   = (const float*)d_in[18];
    const float* m2s_b   = (const float*)d_in[19];
    const float* m2m_w   = (const float*)d_in[20];
    const float* m2m_b   = (const float*)d_in[21];
    const float* alpha   = (const float*)d_in[22];
    const float* tauU    = (const float*)d_in[23];
    float* out = (float*)d_out;

    const size_t smem = (size_t)SMEM_FLOATS * sizeof(float);
    cudaFuncSetAttribute(sgru_main, cudaFuncAttributeMaxDynamicSharedMemorySize, (int)smem);

    zero_flags_kernel<<<1, 128>>>();
    sgru_main<<<NBLK, NTHR, smem>>>(x, h, v, dU, te, tE,
                                    x2h_w, x2h_b, h2h_w, h2h_b,
                                    lnx_g, lnx_b, lnh_g, lnh_b,
                                    h2mod_w, h2mod_b,
                                    m2r_w, m2r_b, m2s_w, m2s_b, m2m_w, m2m_b,
                                    alpha, tauU, out);
}

// round 10
// speedup vs baseline: 1.6732x; 1.0365x over previous
#include <cuda_runtime.h>
#include <cstdint>

#define T_STEPS 64
#define BB      8
#define IN_DIM  256
#define HH      512
#define H3      1536
#define NBLK    128
#define NTHR    512

// ---------------- output offsets (floats) ----------------
#define OUT_V      0ull
#define OUT_H      4096ull
#define OUT_DUF    8192ull
#define OUT_TEF    2105344ull
#define OUT_TEMAT  2109440ull
#define OUT_OUTS   4206592ull
#define OUT_DUS    4468736ull
#define OUT_MODS   138686464ull
#define OUT_SS     138735616ull
#define OUT_MS     138736128ull
#define OUT_RS     138736640ull

// ---------------- smem layout (float index) ----------------
#define S_TEM  0        /* [32][512] trace_E matrix */
#define S_H    16384    /* [8][512] */
#define S_HFW  20480    /* [8][512] */
#define S_TE   24576    /* [8][512] */
#define S_ZW   28672    /* [8][512] zo weight rows */
#define S_NH   32768    /* [512] gate-block new_h */
#define S_FWP  33280    /* [32][4] */
#define S_MOD  33408    /* [96] pad 128 */
#define S_SCAL 33536    /* r[8] s[8] m[8] */
#define S_RED  33568    /* [32] */
#define SMEM_FLOATS 33600
// prologue overlay: sX [0,1024) + wtile [1024,14848) inside S_TEM

// ---------------- device globals ----------------
__device__ float    g_wx[T_STEPS * BB * H3];
__device__ float    g_whbuf[2][BB * H3];
__device__ float    g_h[BB * HH];
__device__ float    g_hfw[BB * HH];
__device__ unsigned g_lineA[NBLK][32];   // [0]=flag (128B padded)
__device__ unsigned g_lineH[BB][32];     // [0]=flag (h/hfw ready)
__device__ unsigned g_lineB[BB][32];     // [0]=flag, [1]=r, [2]=s, [3]=m

// ---------------- helpers ----------------
__device__ __forceinline__ unsigned ld_acq(const unsigned* p) {
    unsigned v;
    asm volatile("ld.global.acquire.gpu.b32 %0, [%1];" : "=r"(v) : "l"(p) : "memory");
    return v;
}
__device__ __forceinline__ void st_rel(unsigned* p, unsigned v) {
    asm volatile("st.global.release.gpu.b32 [%0], %1;" :: "l"(p), "r"(v) : "memory");
}
// warp-0 polls n flag lines (stride 32 per lane); other warps sleep at barrier.
__device__ __forceinline__ void wait_lines_w0(unsigned (*lines)[32], int n, unsigned tgt) {
    if (threadIdx.x < 32) {
        for (;;) {
            int ok = 1;
            for (int k = threadIdx.x; k < n; k += 32)
                ok &= (ld_acq(&lines[k][0]) >= tgt);
            if (__all_sync(0xffffffffu, ok)) break;
        }
    }
    __syncthreads();
}
__device__ __forceinline__ float sigm(float x) { return 1.f / (1.f + __expf(-x)); }
__device__ __forceinline__ float dot4(float4 a, float4 b) {
    return fmaf(a.x, b.x, fmaf(a.y, b.y, fmaf(a.z, b.z, a.w * b.w)));
}
__device__ __forceinline__ float wred(float v) {
#pragma unroll
    for (int o = 16; o; o >>= 1) v += __shfl_down_sync(0xffffffffu, v, o);
    return v;
}
__device__ __forceinline__ float wxor(float v) {
#pragma unroll
    for (int o = 16; o; o >>= 1) v += __shfl_xor_sync(0xffffffffu, v, o);
    return v;
}
__device__ __forceinline__ void block_sum2(float& a, float& b, float* sRed) {
#pragma unroll
    for (int o = 16; o; o >>= 1) {
        a += __shfl_down_sync(0xffffffffu, a, o);
        b += __shfl_down_sync(0xffffffffu, b, o);
    }
    __syncthreads();
    const int w = threadIdx.x >> 5;
    if ((threadIdx.x & 31) == 0) { sRed[w] = a; sRed[16 + w] = b; }
    __syncthreads();
    float ra = 0.f, rb = 0.f;
#pragma unroll
    for (int i = 0; i < 16; i++) { ra += sRed[i]; rb += sRed[16 + i]; }
    a = ra; b = rb;
}

__global__ void zero_flags_kernel() {
    int t = threadIdx.x;
    if (t < NBLK) g_lineA[t][0] = 0u;
    if (t < BB) { g_lineH[t][0] = 0u; g_lineB[t][0] = 0u; }
}

// ====================================================================
__global__ void __launch_bounds__(NTHR, 1)
sgru_main(const float* __restrict__ x,       const float* __restrict__ h_in,
          const float* __restrict__ v_in,    const float* __restrict__ dU_in,
          const float* __restrict__ te_in,   const float* __restrict__ tE_in,
          const float* __restrict__ x2h_w,   const float* __restrict__ x2h_b,
          const float* __restrict__ h2h_w,   const float* __restrict__ h2h_b,
          const float* __restrict__ lnx_g,   const float* __restrict__ lnx_b,
          const float* __restrict__ lnh_g,   const float* __restrict__ lnh_b,
          const float* __restrict__ h2mod_w, const float* __restrict__ h2mod_b,
          const float* __restrict__ m2r_w,   const float* __restrict__ m2r_b,
          const float* __restrict__ m2s_w,   const float* __restrict__ m2s_b,
          const float* __restrict__ m2m_w,   const float* __restrict__ m2m_b,
          const float* __restrict__ alpha_p, const float* __restrict__ tauU_p,
          float* __restrict__ out)
{
    extern __shared__ float sm[];
    const int tid = threadIdx.x;
    const int bk  = blockIdx.x;
    const int wid = tid >> 5, lid = tid & 31;
    const int i0  = bk * 4;
    const int g   = tid >> 7;        // il group 0..3
    const int q   = tid & 127;       // quad index
    const int i   = i0 + g;

    float*  sH    = sm + S_H;
    float*  sHfw  = sm + S_HFW;
    float*  sTe   = sm + S_TE;
    float*  sZW   = sm + S_ZW;
    float*  sNH   = sm + S_NH;
    float*  sFwP  = sm + S_FWP;
    float*  sMod  = sm + S_MOD;
    float*  sScal = sm + S_SCAL;
    float*  sRed  = sm + S_RED;
    float4* sTE4  = (float4*)(sm + S_TEM);
    float4* sH4   = (float4*)sH;
    float4* sHfw4 = (float4*)sHfw;
    float4* sTe4  = (float4*)sTe;

    const float spa     = log1pf(expf(alpha_p[0]));
    const float inv_spe = 1.f / (spa + 1e-8f);
    const float tau     = 1.f / (1.f + expf(-tauU_p[0]));
    const float omtau   = 1.f - tau;

    // ================= PROLOGUE A: g_wx = LN(x @ x2h^T + b) =================
    {
        float* sX    = sm;           // [4][256]
        float* wtile = sm + 1024;    // [1536][9]
        const int rg0 = bk * 4;

        float acc[4][3];
#pragma unroll
        for (int r = 0; r < 4; r++)
#pragma unroll
            for (int p = 0; p < 3; p++) acc[r][p] = 0.f;

        for (int idx = tid; idx < 4 * IN_DIM; idx += NTHR)
            sX[idx] = x[(size_t)rg0 * IN_DIM + idx];

        for (int ct = 0; ct < 32; ++ct) {
            const int c0 = ct * 8;
            __syncthreads();
            for (int idx = tid; idx < H3 * 8; idx += NTHR) {
                int kl = idx >> 3, c = idx & 7;
                wtile[kl * 9 + c] = x2h_w[(size_t)kl * IN_DIM + c0 + c];
            }
            __syncthreads();
            float xv[4][8];
#pragma unroll
            for (int r = 0; r < 4; r++)
#pragma unroll
                for (int c = 0; c < 8; c++) xv[r][c] = sX[r * IN_DIM + c0 + c];
#pragma unroll
            for (int p = 0; p < 3; p++) {
                const int kk = tid + NTHR * p;
                float wv[8];
#pragma unroll
                for (int c = 0; c < 8; c++) wv[c] = wtile[kk * 9 + c];
#pragma unroll
                for (int r = 0; r < 4; r++)
#pragma unroll
                    for (int c = 0; c < 8; c++)
                        acc[r][p] = fmaf(wv[c], xv[r][c], acc[r][p]);
            }
        }
#pragma unroll
        for (int p = 0; p < 3; p++) {
            const float bq = x2h_b[tid + NTHR * p];
#pragma unroll
            for (int r = 0; r < 4; r++) acc[r][p] += bq;
        }
#pragma unroll
        for (int r = 0; r < 4; r++) {
            float s1 = 0.f, s2 = 0.f;
#pragma unroll
            for (int p = 0; p < 3; p++) { float v = acc[r][p]; s1 += v; s2 = fmaf(v, v, s2); }
            block_sum2(s1, s2, sRed);
            const float mu   = s1 * (1.f / H3);
            const float rstd = rsqrtf(s2 * (1.f / H3) - mu * mu + 1e-5f);
            float* wrow = g_wx + (size_t)(rg0 + r) * H3;
#pragma unroll
            for (int p = 0; p < 3; p++) {
                const int kk = tid + NTHR * p;
                wrow[kk] = (acc[r][p] - mu) * rstd * lnx_g[kk] + lnx_b[kk];
            }
        }
        __syncthreads();
    }

    // ================= PROLOGUE B: persistent state =================
    float4 rDU4[8], w4, up4, lo4;
    float vb = 0.f;
    {
        w4 = ((const float4*)(h2h_w + (size_t)(2 * HH + i) * HH))[q];
        up4.x =  fmaxf(1.f - w4.x, 0.f) * inv_spe;  lo4.x = -fmaxf(1.f + w4.x, 0.f) * inv_spe;
        up4.y =  fmaxf(1.f - w4.y, 0.f) * inv_spe;  lo4.y = -fmaxf(1.f + w4.y, 0.f) * inv_spe;
        up4.z =  fmaxf(1.f - w4.z, 0.f) * inv_spe;  lo4.z = -fmaxf(1.f + w4.z, 0.f) * inv_spe;
        up4.w =  fmaxf(1.f - w4.w, 0.f) * inv_spe;  lo4.w = -fmaxf(1.f + w4.w, 0.f) * inv_spe;
#pragma unroll
        for (int b = 0; b < 8; b++) {
            const size_t g4 = (size_t)(b * HH + i) * 128 + q;
            rDU4[b] = ((const float4*)dU_in)[g4];
            sTE4[(g * 8 + b) * 128 + q] = ((const float4*)tE_in)[g4];
        }
        for (int idx = tid; idx < 8 * HH; idx += NTHR) {
            const int w = idx >> 9, j = idx & 511;
            sZW[idx] = h2h_w[(size_t)(bk * 8 + w) * HH + j];
        }
#pragma unroll
        for (int b = 0; b < 8; b++) {
            sTe[b * HH + tid] = te_in[b * HH + tid];
            sH [b * HH + tid] = h_in[b * HH + tid];
        }
        if (bk < BB) vb = v_in[bk * HH + tid];
        __syncthreads();
    }

    // ================= MAIN LOOP =================
    for (int it = 0; it <= T_STEPS; ++it) {
        const bool last = (it == T_STEPS);
        float* whb = g_whbuf[it & 1];

        // ---- wait flagH, load h/hfw ----
        if (it > 0) {
            wait_lines_w0(g_lineH, BB, (unsigned)it);
            const float4* gh4 = (const float4*)g_h;
            const float4* gf4 = (const float4*)g_hfw;
#pragma unroll
            for (int p = 0; p < 2; p++) {
                sH4  [tid + NTHR * p] = __ldcg(&gh4[tid + NTHR * p]);
                sHfw4[tid + NTHR * p] = __ldcg(&gf4[tid + NTHR * p]);
            }
            __syncthreads();
        }

        // ---- zo GEMM (warps 0..7), overlaps gate blocks' mod/scalar tail ----
        if (!last && wid < 8) {
            const int k = bk * 8 + wid;
            float accA[8];
#pragma unroll
            for (int b = 0; b < 8; b++) accA[b] = 0.f;
#pragma unroll
            for (int c = 0; c < 4; c++) {
                const float4 wv = ((const float4*)&sZW[wid * HH])[lid + 32 * c];
#pragma unroll
                for (int b = 0; b < 8; b++)
                    accA[b] += dot4(wv, sH4[b * 128 + lid + 32 * c]);
            }
            const float bias = h2h_b[k];
#pragma unroll
            for (int b = 0; b < 8; b++) {
                float v = wxor(accA[b]);
                if (lid == b) __stcg(&whb[b * H3 + k], v + bias);
            }
        }

        // ---- wait flagB (scalars) ----
        if (it > 0) {
            wait_lines_w0(g_lineB, BB, (unsigned)it);
            if (tid < BB) {
                sScal[tid]      = __ldcg((const float*)&g_lineB[tid][1]);
                sScal[8 + tid]  = __ldcg((const float*)&g_lineB[tid][2]);
                sScal[16 + tid] = __ldcg((const float*)&g_lineB[tid][3]);
            }
            __syncthreads();
        }

        // ---- trace update (step it-1) + fused dv partials ----
        float tnew[8];
#pragma unroll
        for (int b = 0; b < 8; b++) {
            if (it > 0) {
                const float rb  = sScal[b];
                const float sb  = sScal[8 + b];
                const float mb  = sScal[16 + b];
                const float oms = 1.f - sb;
                const float tm  = tau * mb;
                const float hfi = sHfw[b * HH + i];
                const float tei = sTe [b * HH + i];
                const float4 teo4 = sTe4 [b * 128 + q];
                const float4 hf4  = sHfw4[b * 128 + q];
                float4 t4 = sTE4[(g * 8 + b) * 128 + q];
                t4.x = oms * t4.x + sb * (hfi * teo4.x - tei * hf4.x);
                t4.y = oms * t4.y + sb * (hfi * teo4.y - tei * hf4.y);
                t4.z = oms * t4.z + sb * (hfi * teo4.z - tei * hf4.z);
                t4.w = oms * t4.w + sb * (hfi * teo4.w - tei * hf4.w);
                sTE4[(g * 8 + b) * 128 + q] = t4;
                float4 d4 = rDU4[b];
                d4.x = fmaxf(fminf(omtau * d4.x + tm * t4.x, up4.x), lo4.x);
                d4.y = fmaxf(fminf(omtau * d4.y + tm * t4.y, up4.y), lo4.y);
                d4.z = fmaxf(fminf(omtau * d4.z + tm * t4.z, up4.z), lo4.z);
                d4.w = fmaxf(fminf(omtau * d4.w + tm * t4.w, up4.w), lo4.w);
                rDU4[b] = d4;
                tnew[b] = (1.f - rb) * sTe[b * HH + tid] + rb * sHfw[b * HH + tid];
            }
            if (!last) {
                const float4 h4 = sH4[b * 128 + q];
                const float4 d4 = rDU4[b];
                float p = (w4.x + spa * d4.x) * h4.x;
                p = fmaf(w4.y + spa * d4.y, h4.y, p);
                p = fmaf(w4.z + spa * d4.z, h4.z, p);
                p = fmaf(w4.w + spa * d4.w, h4.w, p);
                p = wred(p);
                if (lid == 0) sFwP[(g * 8 + b) * 4 + (wid & 3)] = p;
            }
        }
        __syncthreads();
        if (it > 0) {
#pragma unroll
            for (int b = 0; b < 8; b++) sTe[b * HH + tid] = tnew[b];
        }

        if (last) break;

        // ---- dv combine + publish flagA ----
        if (tid < 32) {
            const float v = sFwP[tid * 4] + sFwP[tid * 4 + 1] + sFwP[tid * 4 + 2] + sFwP[tid * 4 + 3];
            const int b = tid & 7, gg = tid >> 3;
            const int k = 2 * HH + i0 + gg;
            __stcg(&whb[b * H3 + k], v + h2h_b[k]);
        }
        __syncthreads();
        if (tid == 0) st_rel(&g_lineA[bk][0], (unsigned)(it + 1));

        // shadow: dUs(it-1) store (non-gate blocks have until next flagH)
        if (it > 0) {
            float4* dus4 = (float4*)(out + OUT_DUS + (size_t)(it - 1) * (BB * HH * HH));
#pragma unroll
            for (int b = 0; b < 8; b++)
                __stcs(&dus4[(size_t)(b * HH + i) * 128 + q], rDU4[b]);
        }

        // ---- gate blocks: wait all producers, LN + gates -> flagH; mod -> flagB ----
        if (bk < BB) {
            wait_lines_w0(g_lineA, NBLK, (unsigned)(it + 1));
            const int b = bk;
            const float* whrow = whb + b * H3;
            const float p0 = __ldcg(&whrow[tid]);
            const float p1 = __ldcg(&whrow[HH + tid]);
            const float p2 = __ldcg(&whrow[2 * HH + tid]);
            float s1 = p0 + p1 + p2;
            float s2 = fmaf(p0, p0, fmaf(p1, p1, p2 * p2));
            block_sum2(s1, s2, sRed);
            const float mu = s1 * (1.f / H3);
            const float rs = rsqrtf(s2 * (1.f / H3) - mu * mu + 1e-5f);
            const float* wxg = g_wx + (size_t)it * (BB * H3) + b * H3;
            const float pz = (p0 - mu) * rs * lnh_g[tid]          + lnh_b[tid]          + __ldcg(&wxg[tid]);
            const float po = (p1 - mu) * rs * lnh_g[HH + tid]     + lnh_b[HH + tid]     + __ldcg(&wxg[HH + tid]);
            const float pd = (p2 - mu) * rs * lnh_g[2 * HH + tid] + lnh_b[2 * HH + tid] + __ldcg(&wxg[2 * HH + tid]);
            const float z = sigm(pz);
            const float o = sigm(po);
            vb = (1.f - z) * vb + z * pd;
            const float nh = fmaxf(vb, 0.f);
            const float hf = o * nh;
            __stcg(&g_h[b * HH + tid], nh);
            __stcg(&g_hfw[b * HH + tid], hf);
            out[OUT_OUTS + (size_t)it * (BB * HH) + b * HH + tid] = nh;
            sNH[tid] = nh;
            __syncthreads();
            if (tid == 0) st_rel(&g_lineH[b][0], (unsigned)(it + 1));

            // mod = relu(new_h @ h2mod^T + b): 96 rows, 16 warps x 6 rows
            const float4* nh4 = (const float4*)sNH;
            float4 nv[4];
#pragma unroll
            for (int c = 0; c < 4; c++) nv[c] = nh4[lid + 32 * c];
#pragma unroll
            for (int rr = 0; rr < 6; rr++) {
                const int row = wid * 6 + rr;
                const float4* mw = (const float4*)(h2mod_w + (size_t)row * HH);
                float a = 0.f;
#pragma unroll
                for (int c = 0; c < 4; c++) a += dot4(__ldcg(&mw[lid + 32 * c]), nv[c]);
                a = wxor(a);
                if (lid == 0) {
                    const float mv = fmaxf(a + h2mod_b[row], 0.f);
                    sMod[row] = mv;
                    out[OUT_MODS + (size_t)it * (BB * 96) + b * 96 + row] = mv;
                }
            }
            __syncthreads();
            if (wid < 3) {
                const float* ww = (wid == 0) ? m2r_w : (wid == 1) ? m2s_w : m2m_w;
                const float bb0 = (wid == 0) ? m2r_b[0] : (wid == 1) ? m2s_b[0] : m2m_b[0];
                float a = wxor(sMod[wid * 32 + lid] * ww[lid]);
                if (lid == 0) {
                    float val;
                    if (wid == 0) {
                        val = sigm(a + bb0);
                        out[OUT_RS + (size_t)it * BB + b] = val;
                    } else if (wid == 1) {
                        val = sigm(a + bb0);
                        out[OUT_SS + (size_t)it * BB + b] = val;
                    } else {
                        const float mm = a + bb0;
                        val = mm - tanhf(mm);
                        out[OUT_MS + (size_t)it * BB + b] = val;
                    }
                    __stcg((float*)&g_lineB[b][1 + wid], val);
                }
            }
            __syncthreads();
            if (tid == 0) st_rel(&g_lineB[b][0], (unsigned)(it + 1));
        }
    }

    // ================= EPILOGUE =================
    {
        float4* dus4 = (float4*)(out + OUT_DUS + (size_t)(T_STEPS - 1) * (BB * HH * HH));
        float4* duf4 = (float4*)(out + OUT_DUF);
        float4* tem4 = (float4*)(out + OUT_TEMAT);
#pragma unroll
        for (int b = 0; b < 8; b++) {
            const size_t g4 = (size_t)(b * HH + i) * 128 + q;
            dus4[g4] = rDU4[b];
            duf4[g4] = rDU4[b];
            tem4[g4] = sTE4[(g * 8 + b) * 128 + q];
        }
    }
    if (bk < BB) {
        out[OUT_V   + bk * HH + tid] = vb;
        out[OUT_H   + bk * HH + tid] = sH[bk * HH + tid];
        out[OUT_TEF + bk * HH + tid] = sTe[bk * HH + tid];
    }
}

// ====================================================================
extern "C" void kernel_launch(void* const* d_in, const int* in_sizes, int n_in,
                              void* d_out, int out_size) {
    const float* x       = (const float*)d_in[0];
    const float* h       = (const float*)d_in[1];
    const float* v       = (const float*)d_in[2];
    const float* dU      = (const float*)d_in[3];
    const float* te      = (const float*)d_in[4];
    const float* tE      = (const float*)d_in[5];
    const float* x2h_w   = (const float*)d_in[6];
    const float* x2h_b   = (const float*)d_in[7];
    const float* h2h_w   = (const float*)d_in[8];
    const float* h2h_b   = (const float*)d_in[9];
    const float* lnx_g   = (const float*)d_in[10];
    const float* lnx_b   = (const float*)d_in[11];
    const float* lnh_g   = (const float*)d_in[12];
    const float* lnh_b   = (const float*)d_in[13];
    const float* h2mod_w = (const float*)d_in[14];
    const float* h2mod_b = (const float*)d_in[15];
    const float* m2r_w   = (const float*)d_in[16];
    const float* m2r_b   = (const float*)d_in[17];
    const float* m2s_w   = (const float*)d_in[18];
    const float* m2s_b   = (const float*)d_in[19];
    const float* m2m_w   = (const float*)d_in[20];
    const float* m2m_b   = (const float*)d_in[21];
    const float* alpha   = (const float*)d_in[22];
    const float* tauU    = (const float*)d_in[23];
    float* out = (float*)d_out;

    const size_t smem = (size_t)SMEM_FLOATS * sizeof(float);
    cudaFuncSetAttribute(sgru_main, cudaFuncAttributeMaxDynamicSharedMemorySize, (int)smem);

    zero_flags_kernel<<<1, 128>>>();
    sgru_main<<<NBLK, NTHR, smem>>>(x, h, v, dU, te, tE,
                                    x2h_w, x2h_b, h2h_w, h2h_b,
                                    lnx_g, lnx_b, lnh_g, lnh_b,
                                    h2mod_w, h2mod_b,
                                    m2r_w, m2r_b, m2s_w, m2s_b, m2m_w, m2m_b,
                                    alpha, tauU, out);
}

// round 11
// speedup vs baseline: 1.8549x; 1.1086x over previous
#include <cuda_runtime.h>
#include <cstdint>

#define T_STEPS 64
#define BB      8
#define IN_DIM  256
#define HH      512
#define H3      1536
#define NBLK    128
#define NTHR    512

// ---------------- output offsets (floats) ----------------
#define OUT_V      0ull
#define OUT_H      4096ull
#define OUT_DUF    8192ull
#define OUT_TEF    2105344ull
#define OUT_TEMAT  2109440ull
#define OUT_OUTS   4206592ull
#define OUT_DUS    4468736ull
#define OUT_MODS   138686464ull
#define OUT_SS     138735616ull
#define OUT_MS     138736128ull
#define OUT_RS     138736640ull

// ---------------- smem layout (float index) ----------------
#define S_TEM  0        /* [32][512] trace_E rows of this block (batch-local) */
#define S_ZW   16384    /* [64][512] zo weight rows */
#define S_H    49152    /* [512] h_b */
#define S_HFW  49664    /* [512] hfw_b */
#define S_TE   50176    /* [512] te_b */
#define S_NH   50688    /* [512] gate nh */
#define S_FWP  51200    /* [32][4] */
#define S_MOD  51328    /* [96] pad 128 */
#define S_SCAL 51456    /* r,s,m */
#define S_RED  51472    /* [32] */
#define SMEM_FLOATS 51504
// prologue overlay: sX [0,1024) + wtile [1024,14848) inside S_TEM

// ---------------- device globals ----------------
__device__ float    g_wx[T_STEPS * BB * H3];
__device__ float    g_whbuf[2][BB * H3];
__device__ float    g_h[BB * HH];
__device__ float    g_hfw[BB * HH];
__device__ unsigned g_lineA[NBLK][32];   // [0]=flag (128B padded)
__device__ unsigned g_lineH[BB][32];     // [0]=flag
__device__ unsigned g_lineB[BB][32];     // [0]=flag, [1]=r, [2]=s, [3]=m

// ---------------- helpers ----------------
__device__ __forceinline__ unsigned ld_acq(const unsigned* p) {
    unsigned v;
    asm volatile("ld.global.acquire.gpu.b32 %0, [%1];" : "=r"(v) : "l"(p) : "memory");
    return v;
}
__device__ __forceinline__ void st_rel(unsigned* p, unsigned v) {
    asm volatile("st.global.release.gpu.b32 [%0], %1;" :: "l"(p), "r"(v) : "memory");
}
__device__ __forceinline__ void wait_line(unsigned* p, unsigned tgt) {
    if (threadIdx.x == 0) { while (ld_acq(p) < tgt) {} }
    __syncthreads();
}
__device__ __forceinline__ float sigm(float x) { return 1.f / (1.f + __expf(-x)); }
__device__ __forceinline__ float dot4(float4 a, float4 b) {
    return fmaf(a.x, b.x, fmaf(a.y, b.y, fmaf(a.z, b.z, a.w * b.w)));
}
__device__ __forceinline__ float wred(float v) {
#pragma unroll
    for (int o = 16; o; o >>= 1) v += __shfl_down_sync(0xffffffffu, v, o);
    return v;
}
__device__ __forceinline__ void block_sum2(float& a, float& b, float* sRed) {
#pragma unroll
    for (int o = 16; o; o >>= 1) {
        a += __shfl_down_sync(0xffffffffu, a, o);
        b += __shfl_down_sync(0xffffffffu, b, o);
    }
    __syncthreads();
    const int w = threadIdx.x >> 5;
    if ((threadIdx.x & 31) == 0) { sRed[w] = a; sRed[16 + w] = b; }
    __syncthreads();
    float ra = 0.f, rb = 0.f;
#pragma unroll
    for (int i = 0; i < 16; i++) { ra += sRed[i]; rb += sRed[16 + i]; }
    a = ra; b = rb;
}

__global__ void zero_flags_kernel() {
    int t = threadIdx.x;
    if (t < NBLK) g_lineA[t][0] = 0u;
    if (t < BB) { g_lineH[t][0] = 0u; g_lineB[t][0] = 0u; }
}

// ====================================================================
__global__ void __launch_bounds__(NTHR, 1)
sgru_main(const float* __restrict__ x,       const float* __restrict__ h_in,
          const float* __restrict__ v_in,    const float* __restrict__ dU_in,
          const float* __restrict__ te_in,   const float* __restrict__ tE_in,
          const float* __restrict__ x2h_w,   const float* __restrict__ x2h_b,
          const float* __restrict__ h2h_w,   const float* __restrict__ h2h_b,
          const float* __restrict__ lnx_g,   const float* __restrict__ lnx_b,
          const float* __restrict__ lnh_g,   const float* __restrict__ lnh_b,
          const float* __restrict__ h2mod_w, const float* __restrict__ h2mod_b,
          const float* __restrict__ m2r_w,   const float* __restrict__ m2r_b,
          const float* __restrict__ m2s_w,   const float* __restrict__ m2s_b,
          const float* __restrict__ m2m_w,   const float* __restrict__ m2m_b,
          const float* __restrict__ alpha_p, const float* __restrict__ tauU_p,
          float* __restrict__ out)
{
    extern __shared__ float sm[];
    const int tid = threadIdx.x;
    const int bk  = blockIdx.x;
    const int wid = tid >> 5, lid = tid & 31;
    const int b   = bk >> 4;          // batch this block serves
    const int bg  = bk & 15;          // index within batch group
    const bool isGate = (bg == 0);
    const int i0  = bg * 32;          // first owned i-row
    const int g   = tid >> 7;         // row subgroup 0..3
    const int q   = tid & 127;        // quad index (j = 4q..4q+3)

    float*  sH    = sm + S_H;
    float*  sHfw  = sm + S_HFW;
    float*  sTe   = sm + S_TE;
    float*  sNH   = sm + S_NH;
    float*  sFwP  = sm + S_FWP;
    float*  sMod  = sm + S_MOD;
    float*  sScal = sm + S_SCAL;
    float*  sRed  = sm + S_RED;
    float4* sTE4  = (float4*)(sm + S_TEM);
    float4* sZW4  = (float4*)(sm + S_ZW);
    float4* sH4   = (float4*)sH;
    float4* sHfw4 = (float4*)sHfw;
    float4* sTe4  = (float4*)sTe;

    const float spa     = log1pf(expf(alpha_p[0]));
    const float inv_spe = 1.f / (spa + 1e-8f);
    const float tau     = 1.f / (1.f + expf(-tauU_p[0]));
    const float omtau   = 1.f - tau;

    // ================= PROLOGUE A: g_wx = LN(x @ x2h^T + b) =================
    {
        float* sX    = sm;           // [4][256]
        float* wtile = sm + 1024;    // [1536][9]
        const int rg0 = bk * 4;

        float acc[4][3];
#pragma unroll
        for (int r = 0; r < 4; r++)
#pragma unroll
            for (int p = 0; p < 3; p++) acc[r][p] = 0.f;

        for (int idx = tid; idx < 4 * IN_DIM; idx += NTHR)
            sX[idx] = x[(size_t)rg0 * IN_DIM + idx];

        for (int ct = 0; ct < 32; ++ct) {
            const int c0 = ct * 8;
            __syncthreads();
            for (int idx = tid; idx < H3 * 8; idx += NTHR) {
                int kl = idx >> 3, c = idx & 7;
                wtile[kl * 9 + c] = x2h_w[(size_t)kl * IN_DIM + c0 + c];
            }
            __syncthreads();
            float xv[4][8];
#pragma unroll
            for (int r = 0; r < 4; r++)
#pragma unroll
                for (int c = 0; c < 8; c++) xv[r][c] = sX[r * IN_DIM + c0 + c];
#pragma unroll
            for (int p = 0; p < 3; p++) {
                const int kk = tid + NTHR * p;
                float wv[8];
#pragma unroll
                for (int c = 0; c < 8; c++) wv[c] = wtile[kk * 9 + c];
#pragma unroll
                for (int r = 0; r < 4; r++)
#pragma unroll
                    for (int c = 0; c < 8; c++)
                        acc[r][p] = fmaf(wv[c], xv[r][c], acc[r][p]);
            }
        }
#pragma unroll
        for (int p = 0; p < 3; p++) {
            const float bq = x2h_b[tid + NTHR * p];
#pragma unroll
            for (int r = 0; r < 4; r++) acc[r][p] += bq;
        }
#pragma unroll
        for (int r = 0; r < 4; r++) {
            float s1 = 0.f, s2 = 0.f;
#pragma unroll
            for (int p = 0; p < 3; p++) { float v = acc[r][p]; s1 += v; s2 = fmaf(v, v, s2); }
            block_sum2(s1, s2, sRed);
            const float mu   = s1 * (1.f / H3);
            const float rstd = rsqrtf(s2 * (1.f / H3) - mu * mu + 1e-5f);
            float* wrow = g_wx + (size_t)(rg0 + r) * H3;
#pragma unroll
            for (int p = 0; p < 3; p++) {
                const int kk = tid + NTHR * p;
                wrow[kk] = (acc[r][p] - mu) * rstd * lnx_g[kk] + lnx_b[kk];
            }
        }
        __syncthreads();
    }

    // ================= PROLOGUE B: persistent state =================
    float4 rDU4[8], w4r[8];
    float vb = 0.f;
    {
#pragma unroll
        for (int r = 0; r < 8; r++) {
            const int rloc = g * 8 + r;
            const int i    = i0 + rloc;
            const size_t g4 = (size_t)(b * HH + i) * 128 + q;
            rDU4[r] = ((const float4*)dU_in)[g4];
            sTE4[rloc * 128 + q] = ((const float4*)tE_in)[g4];
            w4r[r] = ((const float4*)(h2h_w + (size_t)(2 * HH + i) * HH))[q];
        }
        // zo weight rows [bg*64, bg*64+64) into smem
        for (int idx = tid; idx < 64 * 128; idx += NTHR) {
            const int wloc = idx >> 7, c = idx & 127;
            sZW4[idx] = ((const float4*)(h2h_w + (size_t)(bg * 64 + wloc) * HH))[c];
        }
        sH [tid] = h_in [b * HH + tid];
        sTe[tid] = te_in[b * HH + tid];
        if (isGate) vb = v_in[b * HH + tid];
        __syncthreads();
    }

    // ================= MAIN LOOP =================
    for (int it = 0; it <= T_STEPS; ++it) {
        const bool last = (it == T_STEPS);
        float* whb = g_whbuf[it & 1];

        // ---- consumers: wait flagH, load h_b/hfw_b ----
        if (it > 0 && !isGate) {
            wait_line(&g_lineH[b][0], (unsigned)it);
            sH4  [tid >> 2] = make_float4(0, 0, 0, 0);  // dummy to keep layout; replaced below
            // (load as scalars: 512 threads, 1 each)
            sH  [tid] = __ldcg(&g_h  [b * HH + tid]);
            sHfw[tid] = __ldcg(&g_hfw[b * HH + tid]);
            __syncthreads();
        }

        // ---- zo GEMM: 16 warps x 4 rows ----
        if (!last) {
#pragma unroll
            for (int rr = 0; rr < 4; rr++) {
                const int wloc = wid * 4 + rr;
                const int k    = bg * 64 + wloc;
                float a = 0.f;
#pragma unroll
                for (int c = 0; c < 4; c++)
                    a += dot4(sZW4[wloc * 128 + lid + 32 * c], sH4[lid + 32 * c]);
                a = wred(a);
                if (lid == 0) __stcg(&whb[b * H3 + k], a + h2h_b[k]);
            }
        }

        // ---- consumers: wait flagB, load scalars ----
        if (it > 0 && !isGate) {
            wait_line(&g_lineB[b][0], (unsigned)it);
            if (tid < 3) sScal[tid] = __ldcg((const float*)&g_lineB[b][1 + tid]);
            __syncthreads();
        }

        // ---- trace update (step it-1) + fused dv partials ----
        {
            float rb = 0.f, sb = 0.f, mb = 0.f;
            if (it > 0) { rb = sScal[0]; sb = sScal[1]; mb = sScal[2]; }
            const float oms = 1.f - sb;
            const float tm  = tau * mb;
            const float4 teo4 = sTe4 [q];
            const float4 hf4  = sHfw4[q];
            const float4 h4   = sH4  [q];
#pragma unroll
            for (int r = 0; r < 8; r++) {
                const int rloc = g * 8 + r;
                if (it > 0) {
                    const float hfi = sHfw[i0 + rloc];
                    const float tei = sTe [i0 + rloc];
                    float4 t4 = sTE4[rloc * 128 + q];
                    t4.x = oms * t4.x + sb * (hfi * teo4.x - tei * hf4.x);
                    t4.y = oms * t4.y + sb * (hfi * teo4.y - tei * hf4.y);
                    t4.z = oms * t4.z + sb * (hfi * teo4.z - tei * hf4.z);
                    t4.w = oms * t4.w + sb * (hfi * teo4.w - tei * hf4.w);
                    sTE4[rloc * 128 + q] = t4;
                    const float4 w = w4r[r];
                    float4 d = rDU4[r];
                    d.x = fmaxf(fminf(omtau * d.x + tm * t4.x,  fmaxf(1.f - w.x, 0.f) * inv_spe), -fmaxf(1.f + w.x, 0.f) * inv_spe);
                    d.y = fmaxf(fminf(omtau * d.y + tm * t4.y,  fmaxf(1.f - w.y, 0.f) * inv_spe), -fmaxf(1.f + w.y, 0.f) * inv_spe);
                    d.z = fmaxf(fminf(omtau * d.z + tm * t4.z,  fmaxf(1.f - w.z, 0.f) * inv_spe), -fmaxf(1.f + w.z, 0.f) * inv_spe);
                    d.w = fmaxf(fminf(omtau * d.w + tm * t4.w,  fmaxf(1.f - w.w, 0.f) * inv_spe), -fmaxf(1.f + w.w, 0.f) * inv_spe);
                    rDU4[r] = d;
                }
                if (!last) {
                    const float4 w = w4r[r];
                    const float4 d = rDU4[r];
                    float p = (w.x + spa * d.x) * h4.x;
                    p = fmaf(w.y + spa * d.y, h4.y, p);
                    p = fmaf(w.z + spa * d.z, h4.z, p);
                    p = fmaf(w.w + spa * d.w, h4.w, p);
                    p = wred(p);
                    if (lid == 0) sFwP[rloc * 4 + (wid & 3)] = p;
                }
            }
            __syncthreads();
            if (it > 0) {
                const float tnew = (1.f - rb) * sTe[tid] + rb * sHfw[tid];
                __syncthreads();
                sTe[tid] = tnew;
            }
        }

        if (last) break;

        // ---- dv combine + publish flagA ----
        if (tid < 32) {
            const float v = sFwP[tid * 4] + sFwP[tid * 4 + 1] + sFwP[tid * 4 + 2] + sFwP[tid * 4 + 3];
            const int k = 2 * HH + i0 + tid;
            __stcg(&whb[b * H3 + k], v + h2h_b[k]);
        }
        __syncthreads();
        if (tid == 0) st_rel(&g_lineA[bk][0], (unsigned)(it + 1));

        if (!isGate) {
            // shadow: dUs(it-1)
            if (it > 0) {
                float4* dus4 = (float4*)(out + OUT_DUS + (size_t)(it - 1) * (BB * HH * HH));
#pragma unroll
                for (int r = 0; r < 8; r++)
                    __stcs(&dus4[(size_t)(b * HH + i0 + g * 8 + r) * 128 + q], rDU4[r]);
            }
        } else {
            // ---- gate: wait 16 producers of this batch ----
            if (tid < 32) {
                for (;;) {
                    int ok = 1;
                    if (lid < 16) ok = (ld_acq(&g_lineA[b * 16 + lid][0]) >= (unsigned)(it + 1));
                    if (__all_sync(0xffffffffu, ok)) break;
                }
            }
            __syncthreads();
            // whb load + LN + gates
            const float* whrow = whb + b * H3;
            const float p0 = __ldcg(&whrow[tid]);
            const float p1 = __ldcg(&whrow[HH + tid]);
            const float p2 = __ldcg(&whrow[2 * HH + tid]);
            float s1 = p0 + p1 + p2;
            float s2 = fmaf(p0, p0, fmaf(p1, p1, p2 * p2));
            block_sum2(s1, s2, sRed);
            const float mu = s1 * (1.f / H3);
            const float rs = rsqrtf(s2 * (1.f / H3) - mu * mu + 1e-5f);
            const float* wxg = g_wx + (size_t)it * (BB * H3) + b * H3;
            const float pz = (p0 - mu) * rs * lnh_g[tid]          + lnh_b[tid]          + __ldcg(&wxg[tid]);
            const float po = (p1 - mu) * rs * lnh_g[HH + tid]     + lnh_b[HH + tid]     + __ldcg(&wxg[HH + tid]);
            const float pd = (p2 - mu) * rs * lnh_g[2 * HH + tid] + lnh_b[2 * HH + tid] + __ldcg(&wxg[2 * HH + tid]);
            const float z = sigm(pz);
            const float o = sigm(po);
            vb = (1.f - z) * vb + z * pd;
            const float nh = fmaxf(vb, 0.f);
            const float hf = o * nh;
            __stcg(&g_h  [b * HH + tid], nh);
            __stcg(&g_hfw[b * HH + tid], hf);
            out[OUT_OUTS + (size_t)it * (BB * HH) + b * HH + tid] = nh;
            sNH[tid] = nh;
            __syncthreads();
            sH  [tid] = nh;
            sHfw[tid] = hf;
            if (tid == 0) st_rel(&g_lineH[b][0], (unsigned)(it + 1));

            // mod = relu(nh @ h2mod^T + b): 96 rows / 16 warps
            const float4* nh4 = (const float4*)sNH;
            float4 nv[4];
#pragma unroll
            for (int c = 0; c < 4; c++) nv[c] = nh4[lid + 32 * c];
#pragma unroll
            for (int rr = 0; rr < 6; rr++) {
                const int row = wid * 6 + rr;
                const float4* mw = (const float4*)(h2mod_w + (size_t)row * HH);
                float a = 0.f;
#pragma unroll
                for (int c = 0; c < 4; c++) a += dot4(__ldcg(&mw[lid + 32 * c]), nv[c]);
                a = wred(a);
                if (lid == 0) {
                    const float mv = fmaxf(a + h2mod_b[row], 0.f);
                    sMod[row] = mv;
                    out[OUT_MODS + (size_t)it * (BB * 96) + b * 96 + row] = mv;
                }
            }
            __syncthreads();
            if (wid < 3) {
                const float* ww = (wid == 0) ? m2r_w : (wid == 1) ? m2s_w : m2m_w;
                const float bb0 = (wid == 0) ? m2r_b[0] : (wid == 1) ? m2s_b[0] : m2m_b[0];
                float a = wred(sMod[wid * 32 + lid] * ww[lid]);
                if (lid == 0) {
                    float val;
                    if (wid == 0) {
                        val = sigm(a + bb0);
                        out[OUT_RS + (size_t)it * BB + b] = val;
                    } else if (wid == 1) {
                        val = sigm(a + bb0);
                        out[OUT_SS + (size_t)it * BB + b] = val;
                    } else {
                        const float mm = a + bb0;
                        val = mm - tanhf(mm);
                        out[OUT_MS + (size_t)it * BB + b] = val;
                    }
                    sScal[wid] = val;
                    __stcg((float*)&g_lineB[b][1 + wid], val);
                }
            }
            __syncthreads();
            if (tid == 0) st_rel(&g_lineB[b][0], (unsigned)(it + 1));
            // shadow: dUs(it-1)
            if (it > 0) {
                float4* dus4 = (float4*)(out + OUT_DUS + (size_t)(it - 1) * (BB * HH * HH));
#pragma unroll
                for (int r = 0; r < 8; r++)
                    __stcs(&dus4[(size_t)(b * HH + i0 + g * 8 + r) * 128 + q], rDU4[r]);
            }
        }
    }

    // ================= EPILOGUE =================
    {
        float4* dus4 = (float4*)(out + OUT_DUS + (size_t)(T_STEPS - 1) * (BB * HH * HH));
        float4* duf4 = (float4*)(out + OUT_DUF);
        float4* tem4 = (float4*)(out + OUT_TEMAT);
#pragma unroll
        for (int r = 0; r < 8; r++) {
            const int rloc = g * 8 + r;
            const size_t g4 = (size_t)(b * HH + i0 + rloc) * 128 + q;
            dus4[g4] = rDU4[r];
            duf4[g4] = rDU4[r];
            tem4[g4] = sTE4[rloc * 128 + q];
        }
    }
    if (isGate) {
        out[OUT_V   + b * HH + tid] = vb;
        out[OUT_H   + b * HH + tid] = sH[tid];
        out[OUT_TEF + b * HH + tid] = sTe[tid];
    }
}

// ====================================================================
extern "C" void kernel_launch(void* const* d_in, const int* in_sizes, int n_in,
                              void* d_out, int out_size) {
    const float* x       = (const float*)d_in[0];
    const float* h       = (const float*)d_in[1];
    const float* v       = (const float*)d_in[2];
    const float* dU      = (const float*)d_in[3];
    const float* te      = (const float*)d_in[4];
    const float* tE      = (const float*)d_in[5];
    const float* x2h_w   = (const float*)d_in[6];
    const float* x2h_b   = (const float*)d_in[7];
    const float* h2h_w   = (const float*)d_in[8];
    const float* h2h_b   = (const float*)d_in[9];
    const float* lnx_g   = (const float*)d_in[10];
    const float* lnx_b   = (const float*)d_in[11];
    const float* lnh_g   = (const float*)d_in[12];
    const float* lnh_b   = (const float*)d_in[13];
    const float* h2mod_w = (const float*)d_in[14];
    const float* h2mod_b = (const float*)d_in[15];
    const float* m2r_w   = (const float*)d_in[16];
    const float* m2r_b   = (const float*)d_in[17];
    const float* m2s_w   = (const float*)d_in[18];
    const float* m2s_b   = (const float*)d_in[19];
    const float* m2m_w   = (const float*)d_in[20];
    const float* m2m_b   = (const float*)d_in[21];
    const float* alpha   = (const float*)d_in[22];
    const float* tauU    = (const float*)d_in[23];
    float* out = (float*)d_out;

    const size_t smem = (size_t)SMEM_FLOATS * sizeof(float);
    cudaFuncSetAttribute(sgru_main, cudaFuncAttributeMaxDynamicSharedMemorySize, (int)smem);

    zero_flags_kernel<<<1, 128>>>();
    sgru_main<<<NBLK, NTHR, smem>>>(x, h, v, dU, te, tE,
                                    x2h_w, x2h_b, h2h_w, h2h_b,
                                    lnx_g, lnx_b, lnh_g, lnh_b,
                                    h2mod_w, h2mod_b,
                                    m2r_w, m2r_b, m2s_w, m2s_b, m2m_w, m2m_b,
                                    alpha, tauU, out);
}

// round 12
// speedup vs baseline: 2.0329x; 1.0960x over previous
#include <cuda_runtime.h>
#include <cstdint>

#define T_STEPS 64
#define BB      8
#define IN_DIM  256
#define HH      512
#define H3      1536
#define NBLK    128
#define NTHR    512

// ---------------- output offsets (floats) ----------------
#define OUT_V      0ull
#define OUT_H      4096ull
#define OUT_DUF    8192ull
#define OUT_TEF    2105344ull
#define OUT_TEMAT  2109440ull
#define OUT_OUTS   4206592ull
#define OUT_DUS    4468736ull
#define OUT_MODS   138686464ull
#define OUT_SS     138735616ull
#define OUT_MS     138736128ull
#define OUT_RS     138736640ull

// ---------------- smem layout (float index) ----------------
#define S_TEM  0        /* [32][512] trace_E rows (batch-local) */
#define S_ZW   16384    /* [64][512] zo weight rows */
#define S_H    49152    /* [512] h_b */
#define S_HFW  49664    /* [512] hfw_b */
#define S_TE   50176    /* [512] te_b */
#define S_WX   50688    /* [1536] wx(t) for this batch */
#define S_FWP  52224    /* [32][4] */
#define S_MOD  52352    /* [96] pad 128 */
#define S_SCAL 52480    /* r,s,m */
#define S_RED  52496    /* [32] */
#define SMEM_FLOATS 52528
// prologue overlay: sX [0,1024) + wtile [1024,14848) inside S_TEM/S_ZW

// ---------------- device globals ----------------
__device__ float    g_wx[T_STEPS * BB * H3];
__device__ float    g_whbuf[2][BB * H3];
__device__ unsigned g_lineA[NBLK][32];   // [0]=flag (128B padded)
__device__ unsigned g_lineB[BB][32];     // [0]=flag, [1]=r, [2]=s, [3]=m

// ---------------- helpers ----------------
__device__ __forceinline__ unsigned ld_acq(const unsigned* p) {
    unsigned v;
    asm volatile("ld.global.acquire.gpu.b32 %0, [%1];" : "=r"(v) : "l"(p) : "memory");
    return v;
}
__device__ __forceinline__ void st_rel(unsigned* p, unsigned v) {
    asm volatile("st.global.release.gpu.b32 [%0], %1;" :: "l"(p), "r"(v) : "memory");
}
__device__ __forceinline__ void wait_line(unsigned* p, unsigned tgt) {
    if (threadIdx.x == 0) { while (ld_acq(p) < tgt) {} }
    __syncthreads();
}
__device__ __forceinline__ float sigm(float x) { return 1.f / (1.f + __expf(-x)); }
__device__ __forceinline__ float dot4(float4 a, float4 b) {
    return fmaf(a.x, b.x, fmaf(a.y, b.y, fmaf(a.z, b.z, a.w * b.w)));
}
__device__ __forceinline__ float wred(float v) {
#pragma unroll
    for (int o = 16; o; o >>= 1) v += __shfl_down_sync(0xffffffffu, v, o);
    return v;
}
__device__ __forceinline__ void block_sum2(float& a, float& b, float* sRed) {
#pragma unroll
    for (int o = 16; o; o >>= 1) {
        a += __shfl_down_sync(0xffffffffu, a, o);
        b += __shfl_down_sync(0xffffffffu, b, o);
    }
    __syncthreads();
    const int w = threadIdx.x >> 5;
    if ((threadIdx.x & 31) == 0) { sRed[w] = a; sRed[16 + w] = b; }
    __syncthreads();
    float ra = 0.f, rb = 0.f;
#pragma unroll
    for (int i = 0; i < 16; i++) { ra += sRed[i]; rb += sRed[16 + i]; }
    a = ra; b = rb;
}

__global__ void zero_flags_kernel() {
    int t = threadIdx.x;
    if (t < NBLK) g_lineA[t][0] = 0u;
    if (t < BB)   g_lineB[t][0] = 0u;
}

// ====================================================================
__global__ void __launch_bounds__(NTHR, 1)
sgru_main(const float* __restrict__ x,       const float* __restrict__ h_in,
          const float* __restrict__ v_in,    const float* __restrict__ dU_in,
          const float* __restrict__ te_in,   const float* __restrict__ tE_in,
          const float* __restrict__ x2h_w,   const float* __restrict__ x2h_b,
          const float* __restrict__ h2h_w,   const float* __restrict__ h2h_b,
          const float* __restrict__ lnx_g,   const float* __restrict__ lnx_b,
          const float* __restrict__ lnh_g,   const float* __restrict__ lnh_b,
          const float* __restrict__ h2mod_w, const float* __restrict__ h2mod_b,
          const float* __restrict__ m2r_w,   const float* __restrict__ m2r_b,
          const float* __restrict__ m2s_w,   const float* __restrict__ m2s_b,
          const float* __restrict__ m2m_w,   const float* __restrict__ m2m_b,
          const float* __restrict__ alpha_p, const float* __restrict__ tauU_p,
          float* __restrict__ out)
{
    extern __shared__ float sm[];
    const int tid = threadIdx.x;
    const int bk  = blockIdx.x;
    const int wid = tid >> 5, lid = tid & 31;
    const int b   = bk >> 4;          // batch
    const int bg  = bk & 15;          // index within batch group
    const bool isGate = (bg == 0);
    const int i0  = bg * 32;          // first owned i-row
    const int g   = tid >> 7;         // row subgroup 0..3
    const int q   = tid & 127;        // quad index

    float*  sH    = sm + S_H;
    float*  sHfw  = sm + S_HFW;
    float*  sTe   = sm + S_TE;
    float*  sWX   = sm + S_WX;
    float*  sFwP  = sm + S_FWP;
    float*  sMod  = sm + S_MOD;
    float*  sScal = sm + S_SCAL;
    float*  sRed  = sm + S_RED;
    float4* sTE4  = (float4*)(sm + S_TEM);
    float4* sZW4  = (float4*)(sm + S_ZW);
    float4* sH4   = (float4*)sH;
    float4* sHfw4 = (float4*)sHfw;
    float4* sTe4  = (float4*)sTe;

    const float spa     = log1pf(expf(alpha_p[0]));
    const float inv_spe = 1.f / (spa + 1e-8f);
    const float tau     = 1.f / (1.f + expf(-tauU_p[0]));
    const float omtau   = 1.f - tau;

    // ================= PROLOGUE A: g_wx = LN(x @ x2h^T + b) =================
    {
        float* sX    = sm;           // [4][256]
        float* wtile = sm + 1024;    // [1536][9]
        const int rg0 = bk * 4;

        float acc[4][3];
#pragma unroll
        for (int r = 0; r < 4; r++)
#pragma unroll
            for (int p = 0; p < 3; p++) acc[r][p] = 0.f;

        for (int idx = tid; idx < 4 * IN_DIM; idx += NTHR)
            sX[idx] = x[(size_t)rg0 * IN_DIM + idx];

        for (int ct = 0; ct < 32; ++ct) {
            const int c0 = ct * 8;
            __syncthreads();
            for (int idx = tid; idx < H3 * 8; idx += NTHR) {
                int kl = idx >> 3, c = idx & 7;
                wtile[kl * 9 + c] = x2h_w[(size_t)kl * IN_DIM + c0 + c];
            }
            __syncthreads();
            float xv[4][8];
#pragma unroll
            for (int r = 0; r < 4; r++)
#pragma unroll
                for (int c = 0; c < 8; c++) xv[r][c] = sX[r * IN_DIM + c0 + c];
#pragma unroll
            for (int p = 0; p < 3; p++) {
                const int kk = tid + NTHR * p;
                float wv[8];
#pragma unroll
                for (int c = 0; c < 8; c++) wv[c] = wtile[kk * 9 + c];
#pragma unroll
                for (int r = 0; r < 4; r++)
#pragma unroll
                    for (int c = 0; c < 8; c++)
                        acc[r][p] = fmaf(wv[c], xv[r][c], acc[r][p]);
            }
        }
#pragma unroll
        for (int p = 0; p < 3; p++) {
            const float bq = x2h_b[tid + NTHR * p];
#pragma unroll
            for (int r = 0; r < 4; r++) acc[r][p] += bq;
        }
#pragma unroll
        for (int r = 0; r < 4; r++) {
            float s1 = 0.f, s2 = 0.f;
#pragma unroll
            for (int p = 0; p < 3; p++) { float v = acc[r][p]; s1 += v; s2 = fmaf(v, v, s2); }
            block_sum2(s1, s2, sRed);
            const float mu   = s1 * (1.f / H3);
            const float rstd = rsqrtf(s2 * (1.f / H3) - mu * mu + 1e-5f);
            float* wrow = g_wx + (size_t)(rg0 + r) * H3;
#pragma unroll
            for (int p = 0; p < 3; p++) {
                const int kk = tid + NTHR * p;
                wrow[kk] = (acc[r][p] - mu) * rstd * lnx_g[kk] + lnx_b[kk];
            }
        }
        __syncthreads();
    }

    // ================= PROLOGUE B: persistent state =================
    float4 rDU4[8], w4r[8];
    float vb, lg0, lg1, lg2, lb0, lb1, lb2;
    {
#pragma unroll
        for (int r = 0; r < 8; r++) {
            const int rloc = g * 8 + r;
            const int i    = i0 + rloc;
            const size_t g4 = (size_t)(b * HH + i) * 128 + q;
            rDU4[r] = ((const float4*)dU_in)[g4];
            sTE4[rloc * 128 + q] = ((const float4*)tE_in)[g4];
            w4r[r] = ((const float4*)(h2h_w + (size_t)(2 * HH + i) * HH))[q];
        }
        for (int idx = tid; idx < 64 * 128; idx += NTHR) {
            const int wloc = idx >> 7, c = idx & 127;
            sZW4[idx] = ((const float4*)(h2h_w + (size_t)(bg * 64 + wloc) * HH))[c];
        }
        sH [tid] = h_in [b * HH + tid];
        sTe[tid] = te_in[b * HH + tid];
        vb  = v_in[b * HH + tid];
        lg0 = lnh_g[tid];          lb0 = lnh_b[tid];
        lg1 = lnh_g[HH + tid];     lb1 = lnh_b[HH + tid];
        lg2 = lnh_g[2 * HH + tid]; lb2 = lnh_b[2 * HH + tid];
        __syncthreads();
    }

    // ================= MAIN LOOP =================
    for (int it = 0; it <= T_STEPS; ++it) {
        const bool last = (it == T_STEPS);
        float* whb = g_whbuf[it & 1];

        if (!last) {
            // ---- wx(t) prefetch into smem (no dependencies) ----
            const float* wxg = g_wx + (size_t)it * (BB * H3) + b * H3;
#pragma unroll
            for (int p = 0; p < 3; p++)
                sWX[tid + NTHR * p] = __ldcg(&wxg[tid + NTHR * p]);

            // ---- zo GEMM: 16 warps x 4 rows (uses sH = h(it)) ----
#pragma unroll
            for (int rr = 0; rr < 4; rr++) {
                const int wloc = wid * 4 + rr;
                const int k    = bg * 64 + wloc;
                float a = 0.f;
#pragma unroll
                for (int c = 0; c < 4; c++)
                    a += dot4(sZW4[wloc * 128 + lid + 32 * c], sH4[lid + 32 * c]);
                a = wred(a);
                if (lid == 0) __stcg(&whb[b * H3 + k], a + h2h_b[k]);
            }
        }

        // ---- wait flagB (scalars of step it-1); gate has them locally ----
        if (it > 0 && !isGate) {
            wait_line(&g_lineB[b][0], (unsigned)it);
            if (tid < 3) sScal[tid] = __ldcg((const float*)&g_lineB[b][1 + tid]);
            __syncthreads();
        }

        // ---- trace update (step it-1) + fused dv partials ----
        {
            float rb = 0.f, sb = 0.f, mb = 0.f;
            if (it > 0) { rb = sScal[0]; sb = sScal[1]; mb = sScal[2]; }
            const float oms = 1.f - sb;
            const float tm  = tau * mb;
            const float4 teo4 = sTe4 [q];
            const float4 hf4  = sHfw4[q];
            const float4 h4   = sH4  [q];
#pragma unroll
            for (int r = 0; r < 8; r++) {
                const int rloc = g * 8 + r;
                if (it > 0) {
                    const float hfi = sHfw[i0 + rloc];
                    const float tei = sTe [i0 + rloc];
                    float4 t4 = sTE4[rloc * 128 + q];
                    t4.x = oms * t4.x + sb * (hfi * teo4.x - tei * hf4.x);
                    t4.y = oms * t4.y + sb * (hfi * teo4.y - tei * hf4.y);
                    t4.z = oms * t4.z + sb * (hfi * teo4.z - tei * hf4.z);
                    t4.w = oms * t4.w + sb * (hfi * teo4.w - tei * hf4.w);
                    sTE4[rloc * 128 + q] = t4;
                    const float4 w = w4r[r];
                    float4 d = rDU4[r];
                    d.x = fmaxf(fminf(omtau * d.x + tm * t4.x,  fmaxf(1.f - w.x, 0.f) * inv_spe), -fmaxf(1.f + w.x, 0.f) * inv_spe);
                    d.y = fmaxf(fminf(omtau * d.y + tm * t4.y,  fmaxf(1.f - w.y, 0.f) * inv_spe), -fmaxf(1.f + w.y, 0.f) * inv_spe);
                    d.z = fmaxf(fminf(omtau * d.z + tm * t4.z,  fmaxf(1.f - w.z, 0.f) * inv_spe), -fmaxf(1.f + w.z, 0.f) * inv_spe);
                    d.w = fmaxf(fminf(omtau * d.w + tm * t4.w,  fmaxf(1.f + -w.w, 0.f) * inv_spe), -fmaxf(1.f + w.w, 0.f) * inv_spe);
                    rDU4[r] = d;
                }
                if (!last) {
                    const float4 w = w4r[r];
                    const float4 d = rDU4[r];
                    float p = (w.x + spa * d.x) * h4.x;
                    p = fmaf(w.y + spa * d.y, h4.y, p);
                    p = fmaf(w.z + spa * d.z, h4.z, p);
                    p = fmaf(w.w + spa * d.w, h4.w, p);
                    p = wred(p);
                    if (lid == 0) sFwP[rloc * 4 + (wid & 3)] = p;
                }
            }
            __syncthreads();
            if (it > 0) {
                const float tnew = (1.f - rb) * sTe[tid] + rb * sHfw[tid];
                __syncthreads();
                sTe[tid] = tnew;
            }
        }

        if (last) break;

        // ---- dv combine + publish flagA ----
        if (tid < 32) {
            const float v = sFwP[tid * 4] + sFwP[tid * 4 + 1] + sFwP[tid * 4 + 2] + sFwP[tid * 4 + 3];
            const int k = 2 * HH + i0 + tid;
            __stcg(&whb[b * H3 + k], v + h2h_b[k]);
        }
        __syncthreads();
        if (tid == 0) st_rel(&g_lineA[bk][0], (unsigned)(it + 1));

        // ---- shadow (non-gate): dUs(it-1) store ----
        if (!isGate && it > 0) {
            float4* dus4 = (float4*)(out + OUT_DUS + (size_t)(it - 1) * (BB * HH * HH));
#pragma unroll
            for (int r = 0; r < 8; r++)
                __stcs(&dus4[(size_t)(b * HH + i0 + g * 8 + r) * 128 + q], rDU4[r]);
        }

        // ---- wait all 16 producers of this batch ----
        if (tid < 32) {
            const unsigned* pl = &g_lineA[b * 16 + (lid & 15)][0];
            for (;;) {
                int ok = (ld_acq(pl) >= (unsigned)(it + 1));
                if (__all_sync(0xffffffffu, ok)) break;
            }
        }
        __syncthreads();

        // ---- gates (redundant per batch): whb load + LN + gates -> sH/sHfw ----
        {
            const float* whrow = whb + b * H3;
            const float p0 = __ldcg(&whrow[tid]);
            const float p1 = __ldcg(&whrow[HH + tid]);
            const float p2 = __ldcg(&whrow[2 * HH + tid]);
            float s1 = p0 + p1 + p2;
            float s2 = fmaf(p0, p0, fmaf(p1, p1, p2 * p2));
            block_sum2(s1, s2, sRed);
            const float mu = s1 * (1.f / H3);
            const float rs = rsqrtf(s2 * (1.f / H3) - mu * mu + 1e-5f);
            const float pz = (p0 - mu) * rs * lg0 + lb0 + sWX[tid];
            const float po = (p1 - mu) * rs * lg1 + lb1 + sWX[HH + tid];
            const float pd = (p2 - mu) * rs * lg2 + lb2 + sWX[2 * HH + tid];
            const float z = sigm(pz);
            const float o = sigm(po);
            vb = (1.f - z) * vb + z * pd;
            const float nh = fmaxf(vb, 0.f);
            const float hf = o * nh;
            sH  [tid] = nh;
            sHfw[tid] = hf;
            if (isGate)
                out[OUT_OUTS + (size_t)it * (BB * HH) + b * HH + tid] = nh;
        }
        __syncthreads();

        // ---- gate only: mod + scalars -> flagB; then shadow dUs ----
        if (isGate) {
            const float4* nh4 = (const float4*)sH;
            float4 nv[4];
#pragma unroll
            for (int c = 0; c < 4; c++) nv[c] = nh4[lid + 32 * c];
#pragma unroll
            for (int rr = 0; rr < 6; rr++) {
                const int row = wid * 6 + rr;
                const float4* mw = (const float4*)(h2mod_w + (size_t)row * HH);
                float a = 0.f;
#pragma unroll
                for (int c = 0; c < 4; c++) a += dot4(__ldcg(&mw[lid + 32 * c]), nv[c]);
                a = wred(a);
                if (lid == 0) {
                    const float mv = fmaxf(a + h2mod_b[row], 0.f);
                    sMod[row] = mv;
                    out[OUT_MODS + (size_t)it * (BB * 96) + b * 96 + row] = mv;
                }
            }
            __syncthreads();
            if (wid < 3) {
                const float* ww = (wid == 0) ? m2r_w : (wid == 1) ? m2s_w : m2m_w;
                const float bb0 = (wid == 0) ? m2r_b[0] : (wid == 1) ? m2s_b[0] : m2m_b[0];
                float a = wred(sMod[wid * 32 + lid] * ww[lid]);
                if (lid == 0) {
                    float val;
                    if (wid == 0) {
                        val = sigm(a + bb0);
                        out[OUT_RS + (size_t)it * BB + b] = val;
                    } else if (wid == 1) {
                        val = sigm(a + bb0);
                        out[OUT_SS + (size_t)it * BB + b] = val;
                    } else {
                        const float mm = a + bb0;
                        val = mm - tanhf(mm);
                        out[OUT_MS + (size_t)it * BB + b] = val;
                    }
                    sScal[wid] = val;
                    __stcg((float*)&g_lineB[b][1 + wid], val);
                }
            }
            __syncthreads();
            if (tid == 0) st_rel(&g_lineB[b][0], (unsigned)(it + 1));
            if (it > 0) {
                float4* dus4 = (float4*)(out + OUT_DUS + (size_t)(it - 1) * (BB * HH * HH));
#pragma unroll
                for (int r = 0; r < 8; r++)
                    __stcs(&dus4[(size_t)(b * HH + i0 + g * 8 + r) * 128 + q], rDU4[r]);
            }
        }
    }

    // ================= EPILOGUE =================
    {
        float4* dus4 = (float4*)(out + OUT_DUS + (size_t)(T_STEPS - 1) * (BB * HH * HH));
        float4* duf4 = (float4*)(out + OUT_DUF);
        float4* tem4 = (float4*)(out + OUT_TEMAT);
#pragma unroll
        for (int r = 0; r < 8; r++) {
            const int rloc = g * 8 + r;
            const size_t g4 = (size_t)(b * HH + i0 + rloc) * 128 + q;
            dus4[g4] = rDU4[r];
            duf4[g4] = rDU4[r];
            tem4[g4] = sTE4[rloc * 128 + q];
        }
    }
    if (isGate) {
        out[OUT_V   + b * HH + tid] = vb;
        out[OUT_H   + b * HH + tid] = sH[tid];
        out[OUT_TEF + b * HH + tid] = sTe[tid];
    }
}

// ====================================================================
extern "C" void kernel_launch(void* const* d_in, const int* in_sizes, int n_in,
                              void* d_out, int out_size) {
    const float* x       = (const float*)d_in[0];
    const float* h       = (const float*)d_in[1];
    const float* v       = (const float*)d_in[2];
    const float* dU      = (const float*)d_in[3];
    const float* te      = (const float*)d_in[4];
    const float* tE      = (const float*)d_in[5];
    const float* x2h_w   = (const float*)d_in[6];
    const float* x2h_b   = (const float*)d_in[7];
    const float* h2h_w   = (const float*)d_in[8];
    const float* h2h_b   = (const float*)d_in[9];
    const float* lnx_g   = (const float*)d_in[10];
    const float* lnx_b   = (const float*)d_in[11];
    const float* lnh_g   = (const float*)d_in[12];
    const float* lnh_b   = (const float*)d_in[13];
    const float* h2mod_w = (const float*)d_in[14];
    const float* h2mod_b = (const float*)d_in[15];
    const float* m2r_w   = (const float*)d_in[16];
    const float* m2r_b   = (const float*)d_in[17];
    const float* m2s_w   = (const float*)d_in[18];
    const float* m2s_b   = (const float*)d_in[19];
    const float* m2m_w   = (const float*)d_in[20];
    const float* m2m_b   = (const float*)d_in[21];
    const float* alpha   = (const float*)d_in[22];
    const float* tauU    = (const float*)d_in[23];
    float* out = (float*)d_out;

    const size_t smem = (size_t)SMEM_FLOATS * sizeof(float);
    cudaFuncSetAttribute(sgru_main, cudaFuncAttributeMaxDynamicSharedMemorySize, (int)smem);

    zero_flags_kernel<<<1, 128>>>();
    sgru_main<<<NBLK, NTHR, smem>>>(x, h, v, dU, te, tE,
                                    x2h_w, x2h_b, h2h_w, h2h_b,
                                    lnx_g, lnx_b, lnh_g, lnh_b,
                                    h2mod_w, h2mod_b,
                                    m2r_w, m2r_b, m2s_w, m2s_b, m2m_w, m2m_b,
                                    alpha, tauU, out);
}